// round 11
// baseline (speedup 1.0000x reference)
#include <cuda_runtime.h>
#include <cuda_bf16.h>
#include <math.h>
#include <stdint.h>

// Problem dims
#define BB 256
#define TT 512
#define FF 256
#define HH 512
#define G4 2048
#define EE 128
#define NREC 128   // persistent CTAs (4 mt-groups x 32 nt)

// ---- device-global scratch (no allocations allowed) ----
__device__ float         g_gx[(size_t)TT * BB * G4];   // [T][B][4H] permuted input proj (+bias)
__device__ __nv_bfloat16 g_Wphi[(size_t)G4 * HH];      // permuted W_hh (bf16)
__device__ __nv_bfloat16 g_Wihphi[(size_t)G4 * FF];    // permuted W_ih (bf16)
__device__ float         g_biasp[G4];                  // permuted b_ih + b_hh
__device__ __nv_bfloat16 g_hhi[BB * HH];               // final h hi (for fc)
__device__ __nv_bfloat16 g_hlo[BB * HH];               // final h lo (for fc)
// h state in MMA A-fragment layout, double-buffered (WAR-safe under epochs):
// [2][ (mt*4+wm)*32 + kc ][ lane ] -> uint4
__device__ uint4         g_hfrag[2][16384];
// per-CTA epoch flags: one 128B line per mt, single-owner stores (no RMW)
__device__ __align__(128) unsigned g_epoch[4][32];

// ---------------------------------------------------------------------------
// helpers
// ---------------------------------------------------------------------------
__device__ __forceinline__ uint32_t smem_u32(const void* p) {
    uint32_t a;
    asm("{ .reg .u64 t; cvta.to.shared.u64 t, %1; cvt.u32.u64 %0, t; }" : "=r"(a) : "l"(p));
    return a;
}
__device__ __forceinline__ float sigf(float x)   { return 1.f / (1.f + __expf(-x)); }
__device__ __forceinline__ float tanhfa(float x) { return 2.f / (1.f + __expf(-2.f * x)) - 1.f; }
__device__ __forceinline__ float tha(float x) {
    float y; asm("tanh.approx.f32 %0, %1;" : "=f"(y) : "f"(x)); return y;
}
__device__ __forceinline__ float sga(float x) { return fmaf(tha(0.5f * x), 0.5f, 0.5f); }

__device__ __forceinline__ uint32_t pack2hi(float a, float b) {
    __nv_bfloat162 h = __floats2bfloat162_rn(a, b);
    return reinterpret_cast<uint32_t&>(h);
}

__device__ __forceinline__ void ldsm4(uint32_t (&r)[4], uint32_t addr) {
    asm volatile("ldmatrix.sync.aligned.m8n8.x4.shared.b16 {%0,%1,%2,%3}, [%4];"
        : "=r"(r[0]), "=r"(r[1]), "=r"(r[2]), "=r"(r[3]) : "r"(addr));
}
__device__ __forceinline__ void mma16816(float (&c)[4], const uint32_t (&a)[4],
                                         const uint32_t b0, const uint32_t b1) {
    asm volatile("mma.sync.aligned.m16n8k16.row.col.f32.bf16.bf16.f32 "
        "{%0,%1,%2,%3}, {%4,%5,%6,%7}, {%8,%9}, {%0,%1,%2,%3};"
        : "+f"(c[0]), "+f"(c[1]), "+f"(c[2]), "+f"(c[3])
        : "r"(a[0]), "r"(a[1]), "r"(a[2]), "r"(a[3]), "r"(b0), "r"(b1));
}
__device__ __forceinline__ uint4 ldg_cg(const uint4* p) {
    uint4 v;
    asm volatile("ld.global.cg.v4.u32 {%0,%1,%2,%3}, [%4];"
        : "=r"(v.x), "=r"(v.y), "=r"(v.z), "=r"(v.w) : "l"(p));
    return v;
}
__device__ __forceinline__ unsigned ldg_cg_u32(const unsigned* p) {
    unsigned v;
    asm volatile("ld.global.cg.u32 %0, [%1];" : "=r"(v) : "l"(p));
    return v;
}

// ---------------------------------------------------------------------------
// 1-term MMA chunk: acc += A * W. NF n-fragments. (gx kernel)
// ---------------------------------------------------------------------------
template<int NF>
__device__ __forceinline__ void mma_chunk1g(
    const uint32_t aBase, const uint32_t wHi,
    const int wRowB, const int kw0, const int wm, const int wn, const int lane,
    float (&acc)[2][NF][4])
{
    const int la  = lane & 15;
    const int aKo = (lane & 16) ? 16 : 0;
    const int nB  = wn * (NF * 8) + (lane & 7) + ((lane & 16) ? 8 : 0);
    const int bKo = (lane & 8) ? 16 : 0;
    const int m0w = wm * 32;

#pragma unroll
    for (int kk = 0; kk < 4; kk++) {
        const int kb = kk * 32;
        uint32_t ah[2][4];
#pragma unroll
        for (int mf = 0; mf < 2; mf++) {
            int m = m0w + mf * 16 + la;
            uint32_t off = (uint32_t)(m * 128 + ((kb + aKo) ^ ((m & 7) << 4)));
            ldsm4(ah[mf], aBase + off);
        }
        uint32_t bh[NF][2];
#pragma unroll
        for (int nh = 0; nh < NF / 2; nh++) {
            int n = nB + nh * 16;
            uint32_t off = (uint32_t)(n * wRowB + ((kw0 + kb + bKo) ^ ((n & 7) << 4)));
            uint32_t r[4];
            ldsm4(r, wHi + off);
            bh[nh*2][0] = r[0]; bh[nh*2][1] = r[1];
            bh[nh*2+1][0] = r[2]; bh[nh*2+1][1] = r[3];
        }
#pragma unroll
        for (int mf = 0; mf < 2; mf++)
#pragma unroll
            for (int nf = 0; nf < NF; nf++)
                mma16816(acc[mf][nf], ah[mf], bh[nf][0], bh[nf][1]);
    }
}

// ---------------------------------------------------------------------------
// prep: permute W_hh/W_ih/bias to gate-interleaved columns (bf16).
// unit j, gate g: group=j/4, q=j%4 -> cols group*16 + {2q,2q+1,8+2q,9+2q}
// Also write h0 (bf16) into fragment-layout buffer 0.
// ---------------------------------------------------------------------------
__global__ void prep_kernel(const float* __restrict__ Whh, const float* __restrict__ Wih,
                            const float* __restrict__ bih, const float* __restrict__ bhh,
                            const float* __restrict__ h0)
{
    const int n = blockIdx.x;
    const int group = n >> 4, wi = n & 15;
    const int gate = ((wi >> 3) << 1) | (wi & 1);
    const int j = (group << 2) | ((wi & 7) >> 1);
    const int o = gate * HH + j;
    const int tid = threadIdx.x;

    {
        int k2 = tid * 2;
        uint32_t hi = pack2hi(Whh[(size_t)o * HH + k2], Whh[(size_t)o * HH + k2 + 1]);
        *(uint32_t*)&g_Wphi[(size_t)n * HH + k2] = hi;
    }
    if (tid < 128) {
        int k2 = tid * 2;
        uint32_t hi = pack2hi(Wih[(size_t)o * FF + k2], Wih[(size_t)o * FF + k2 + 1]);
        *(uint32_t*)&g_Wihphi[(size_t)n * FF + k2] = hi;
    }
    if (tid == 0) g_biasp[n] = bih[o] + bhh[o];
    if (n < BB) {   // h0 -> fragment layout (buffer 0)
        const int m = n;
        const int mt = m >> 6, mloc = m & 63, wm = mloc >> 4, row16 = mloc & 15;
        const int r8 = row16 & 7, aR = row16 >> 3;
#pragma unroll
        for (int e = 0; e < 2; e++) {
            int jd = tid * 2 + e;
            __nv_bfloat16 hi = __float2bfloat16(h0[(size_t)m * HH + jd]);
            int kc = jd >> 4, jc = jd & 15, p = (jc >> 1) & 3, aC = jc >> 3;
            size_t hw = ((size_t)((mt * 4 + wm) * 32 + kc) * 32 + (r8 * 4 + p)) * 8
                        + (aC * 2 + aR) * 2 + (jd & 1);
            ((__nv_bfloat16*)g_hfrag)[hw] = hi;
        }
    }
}

// ---------------------------------------------------------------------------
// Phase 1: gx = x @ Wihp^T + biasp (1-term bf16). Tile 128M x 64N, 4 iters.
// grid (32 nt, 256 mo). 8 warps: wm=w&3, wn=w>>2 (NF=4).
// smem: W 32KB @0 (rowB=512), A dbl-buf @32768 (2 x 16KB)
// ---------------------------------------------------------------------------
#define GX_SMEM 65536
__global__ void __launch_bounds__(256, 1) gx_kernel(const float* __restrict__ x)
{
    extern __shared__ char sm[];
    const uint32_t smu = smem_u32(sm);
    const int tid = threadIdx.x, w = tid >> 5, lane = tid & 31;
    const int wm = w & 3, wn = w >> 2;
    const int nt = blockIdx.x;
    const int n0 = nt * 64;
    const int q = lane & 3, r = lane >> 2;

    // resident W_ih (64 rows x 256 k, bf16): 2048 granules of 16B
#pragma unroll
    for (int i = 0; i < 8; i++) {
        int c = tid + i * 256;
        int n = c >> 5, g = c & 31;
        uint4 v = *(const uint4*)((const char*)g_Wihphi + (size_t)(n0 + n) * 512 + g * 16);
        *(uint4*)(sm + n * 512 + ((g * 16) ^ ((n & 7) << 4))) = v;
    }
    float2 bias2[4];
#pragma unroll
    for (int nf = 0; nf < 4; nf++)
        bias2[nf] = *(const float2*)&g_biasp[n0 + wn * 32 + nf * 8 + 2 * q];
    __syncthreads();

    uint4 shi[4];
#define GX_LD(kc, m0) do { \
    _Pragma("unroll") \
    for (int i2 = 0; i2 < 4; i2++) { \
        int c = tid + i2 * 256; int m = c >> 3, g = c & 7; \
        const float* sp = x + (size_t)((m0) + m) * FF + (kc) * 64 + g * 8; \
        float4 f0 = *(const float4*)sp; float4 f1 = *(const float4*)(sp + 4); \
        shi[i2].x = pack2hi(f0.x, f0.y); shi[i2].y = pack2hi(f0.z, f0.w); \
        shi[i2].z = pack2hi(f1.x, f1.y); shi[i2].w = pack2hi(f1.z, f1.w); \
    } } while (0)
#define GX_ST(buf) do { \
    _Pragma("unroll") \
    for (int i2 = 0; i2 < 4; i2++) { \
        int c = tid + i2 * 256; int m = c >> 3, g = c & 7; \
        *(uint4*)(sm + 32768 + (buf) * 16384 + m * 128 + ((g * 16) ^ ((m & 7) << 4))) = shi[i2]; \
    } } while (0)

    for (int it = 0; it < 4; it++) {
        const int m0 = blockIdx.y * 512 + it * 128;

        float acc[2][4][4];
#pragma unroll
        for (int a = 0; a < 2; a++)
#pragma unroll
            for (int b = 0; b < 4; b++)
#pragma unroll
                for (int cidx = 0; cidx < 4; cidx++) acc[a][b][cidx] = 0.f;

        GX_LD(0, m0); GX_ST(0); __syncthreads();
#pragma unroll
        for (int kc = 0; kc < 4; kc++) {
            if (kc < 3) GX_LD(kc + 1, m0);
            mma_chunk1g<4>(smu + 32768 + (kc & 1) * 16384, smu,
                           512, kc * 128, wm, wn, lane, acc);
            if (kc < 3) { GX_ST((kc + 1) & 1); __syncthreads(); }
        }

#pragma unroll
        for (int mf = 0; mf < 2; mf++)
#pragma unroll
            for (int rp = 0; rp < 2; rp++) {
                int m = m0 + wm * 32 + mf * 16 + r + rp * 8;
                int t = m & (TT - 1), b = m >> 9;
                float* dst = g_gx + ((size_t)t * BB + b) * G4;
#pragma unroll
                for (int nf = 0; nf < 4; nf++) {
                    int col = n0 + wn * 32 + nf * 8 + 2 * q;
                    *(float2*)(dst + col) =
                        make_float2(acc[mf][nf][rp*2+0] + bias2[nf].x,
                                    acc[mf][nf][rp*2+1] + bias2[nf].y);
                }
            }
        __syncthreads();
    }
}

// ---------------------------------------------------------------------------
// Phase 2: warp-autonomous persistent recurrent kernel.
// R7 loop shape (branch-free LDG prefetch ring), but release via TWO-LEVEL
// arrive: 8 warps -> smem counter (ATOMS); last warp stores epoch t+1 to
// g_epoch[mt][nt] (plain store, no global RMW). Readers poll one 128B flag
// line (coalesced) + __all_sync, split into two phases overlapping MMA.
// 128 CTAs x 256 thr; mt = bx&3, nt = bx>>2; 8 warps = 4 wm x 2 wn.
// smem: W 64KB @0; pack scratch 2KB @65536; arrive counter @67584.
// ---------------------------------------------------------------------------
#define LSTM_SMEM 67712
__global__ void __launch_bounds__(256, 1) lstm_kernel(const float* __restrict__ c0)
{
    extern __shared__ char sm[];
    const uint32_t smu = smem_u32(sm);
    const int tid = threadIdx.x, w = tid >> 5, lane = tid & 31;
    const int wm = w & 3, wn = w >> 2;
    const int bx = blockIdx.x;
    const int mt = bx & 3, nt = bx >> 2;
    const int m0 = mt * 64, n0 = nt * 64;
    const int q = lane & 3, r = lane >> 2;
    unsigned* scnt = (unsigned*)(sm + 67584);

    // resident W (64 perm-cols x 512 k, bf16)
#pragma unroll
    for (int i = 0; i < 16; i++) {
        int c = tid + i * 256;
        int n = c >> 6, g = c & 63;
        uint4 v = *(const uint4*)((const char*)g_Wphi + (size_t)(n0 + n) * 1024 + g * 16);
        *(uint4*)(sm + n * 1024 + ((g * 16) ^ ((n & 7) << 4))) = v;
    }
    if (tid == 0) *scnt = 0;

    const int mr0 = m0 + wm * 16 + r;
    const int unitA = (nt * 4 + wn * 2) * 4 + q;
    const int unitB = unitA + 4;

    float creg[4];
    creg[0] = c0[(size_t)mr0 * HH + unitA];
    creg[1] = c0[(size_t)(mr0 + 8) * HH + unitA];
    creg[2] = c0[(size_t)mr0 * HH + unitB];
    creg[3] = c0[(size_t)(mr0 + 8) * HH + unitB];
    __syncthreads();    // W + scnt ready (only CTA-wide sync; outside the loop)

    // ldsm W addressing
    const int nW1 = wn * 32 + (lane & 7) + ((lane & 16) ? 8 : 0);
    const int nW2 = nW1 + 16;
    const int bKo = (lane & 8) ? 16 : 0;
    const uint32_t wb1 = smu + nW1 * 1024;
    const uint32_t wb2 = smu + nW2 * 1024;
    const int sw1 = (nW1 & 7) << 4, sw2 = (nW2 & 7) << 4;

    const int colA = n0 + wn * 32 + 2 * q;
    const int fragbase = ((mt * 4 + wm) * 32) * 32 + lane;
    const uint32_t ps = smu + 65536 + w * 256;
    const unsigned* ep = &g_epoch[mt][0];

    for (int t = 0; t < TT; t++) {
        // ---- gx loads (immutable; issued before the wait, overlap polling) ----
        const float* gp0 = g_gx + ((size_t)t * BB + mr0) * G4;
        const float* gp1 = gp0 + 8 * G4;
        float2 ifA0 = *(const float2*)(gp0 + colA);
        float2 goA0 = *(const float2*)(gp0 + colA + 8);
        float2 ifB0 = *(const float2*)(gp0 + colA + 16);
        float2 goB0 = *(const float2*)(gp0 + colA + 24);
        float2 ifA1 = *(const float2*)(gp1 + colA);
        float2 goA1 = *(const float2*)(gp1 + colA + 8);
        float2 ifB1 = *(const float2*)(gp1 + colA + 16);
        float2 goB1 = *(const float2*)(gp1 + colA + 24);

        const unsigned tgt = (unsigned)t;
        const uint4* hin = &g_hfrag[t & 1][fragbase];

        // ---- phase-A wait: producer CTAs nt 0..15 published epoch >= t ----
        if (t) {
            while (1) {
                unsigned f = ldg_cg_u32(ep + lane);
                if (__all_sync(0xffffffffu, (lane >= 16) | (f >= tgt))) break;
                __nanosleep(64);
            }
        }
        __threadfence();   // acquire

        float acc[4][4];
#pragma unroll
        for (int a = 0; a < 4; a++)
#pragma unroll
            for (int cix = 0; cix < 4; cix++) acc[a][cix] = 0.f;

        uint4 ab[8];
#pragma unroll
        for (int i = 0; i < 8; i++) ab[i] = ldg_cg(hin + i * 32);
#pragma unroll
        for (int kc = 0; kc < 8; kc++) {   // chunks 0..7, prefetch 8..15 (phase-A data)
            uint32_t au[4] = { ab[kc & 7].x, ab[kc & 7].y, ab[kc & 7].z, ab[kc & 7].w };
            ab[kc & 7] = ldg_cg(hin + (kc + 8) * 32);
            uint32_t rA[4], rB[4];
            ldsm4(rA, wb1 + (uint32_t)((kc * 32 + bKo) ^ sw1));
            ldsm4(rB, wb2 + (uint32_t)((kc * 32 + bKo) ^ sw2));
            mma16816(acc[0], au, rA[0], rA[1]);
            mma16816(acc[1], au, rA[2], rA[3]);
            mma16816(acc[2], au, rB[0], rB[1]);
            mma16816(acc[3], au, rB[2], rB[3]);
        }

        // ---- phase-B wait: producer CTAs nt 16..31 ----
        if (t) {
            while (1) {
                unsigned f = ldg_cg_u32(ep + lane);
                if (__all_sync(0xffffffffu, (lane < 16) | (f >= tgt))) break;
                __nanosleep(64);
            }
        }
#pragma unroll
        for (int kc = 8; kc < 32; kc++) {
            uint32_t au[4] = { ab[kc & 7].x, ab[kc & 7].y, ab[kc & 7].z, ab[kc & 7].w };
            if (kc < 24) ab[kc & 7] = ldg_cg(hin + (kc + 8) * 32);
            uint32_t rA[4], rB[4];
            ldsm4(rA, wb1 + (uint32_t)((kc * 32 + bKo) ^ sw1));
            ldsm4(rB, wb2 + (uint32_t)((kc * 32 + bKo) ^ sw2));
            mma16816(acc[0], au, rA[0], rA[1]);
            mma16816(acc[1], au, rA[2], rA[3]);
            mma16816(acc[2], au, rB[0], rB[1]);
            mma16816(acc[3], au, rB[2], rB[3]);
        }

        // ---- epilogue: gates + state update (approx gates; exact last step) ----
        const bool last = (t == TT - 1);
        float hv[4];
        float sI[4], sF[4], sG[4], sO[4];
        sI[0] = acc[0][0] + ifA0.x;  sF[0] = acc[0][1] + ifA0.y;
        sG[0] = acc[1][0] + goA0.x;  sO[0] = acc[1][1] + goA0.y;
        sI[1] = acc[0][2] + ifA1.x;  sF[1] = acc[0][3] + ifA1.y;
        sG[1] = acc[1][2] + goA1.x;  sO[1] = acc[1][3] + goA1.y;
        sI[2] = acc[2][0] + ifB0.x;  sF[2] = acc[2][1] + ifB0.y;
        sG[2] = acc[3][0] + goB0.x;  sO[2] = acc[3][1] + goB0.y;
        sI[3] = acc[2][2] + ifB1.x;  sF[3] = acc[2][3] + ifB1.y;
        sG[3] = acc[3][2] + goB1.x;  sO[3] = acc[3][3] + goB1.y;
#pragma unroll
        for (int cell = 0; cell < 4; cell++) {
            float iv, fv, gv, ov, cc;
            if (!last) {
                iv = sga(sI[cell]); fv = sga(sF[cell]);
                gv = tha(sG[cell]); ov = sga(sO[cell]);
                cc = fv * creg[cell] + iv * gv;
                hv[cell] = ov * tha(cc);
            } else {
                iv = sigf(sI[cell]); fv = sigf(sF[cell]);
                gv = tanhfa(sG[cell]); ov = sigf(sO[cell]);
                cc = fv * creg[cell] + iv * gv;
                hv[cell] = ov * tanhfa(cc);
            }
            creg[cell] = cc;
        }

        // ---- pack h into A-fragment words (warp-local smem), publish ----
#pragma unroll
        for (int cell = 0; cell < 4; cell++) {
            int rp = cell & 1, g = cell >> 1;
            unsigned short hb;
            __nv_bfloat16 b16 = __float2bfloat16(hv[cell]);
            hb = *(unsigned short*)&b16;
            uint32_t addr = ps + (uint32_t)((r + rp * 8) * 16 + (g * 4 + q) * 2);
            asm volatile("st.shared.u16 [%0], %1;" :: "r"(addr), "h"(hb));
        }
        __syncwarp();
        {
            uint32_t v0, v1;
            asm volatile("ld.shared.u32 %0, [%1];" : "=r"(v0)
                         : "r"(ps + (uint32_t)((lane >> 2) * 16 + (lane & 3) * 4)));
            asm volatile("ld.shared.u32 %0, [%1];" : "=r"(v1)
                         : "r"(ps + (uint32_t)(((lane >> 2) + 8) * 16 + (lane & 3) * 4)));
            uint2 outw = make_uint2(v0, v1);
            uint2* hop = (uint2*)&g_hfrag[(t + 1) & 1][((mt * 4 + wm) * 32 + nt) * 32];
            hop[lane * 2 + wn] = outw;
        }

        if (last) {   // also publish original-layout h (hi+lo) for fc
#pragma unroll
            for (int cell = 0; cell < 4; cell++) {
                int rp = cell & 1, g = cell >> 1;
                int m = mr0 + rp * 8;
                int u = g ? unitB : unitA;
                __nv_bfloat16 hi = __float2bfloat16(hv[cell]);
                g_hhi[(size_t)m * HH + u] = hi;
                g_hlo[(size_t)m * HH + u] = __float2bfloat16(hv[cell] - __bfloat162float(hi));
            }
        }

        // ---- two-level release: fence, smem arrive; last warp stores epoch ----
        __threadfence();
        if (lane == 0) {
            unsigned old = atomicAdd(scnt, 1u);
            if (old == 8u * (unsigned)(t + 1) - 1u) {
                __threadfence();
                asm volatile("st.global.cg.u32 [%0], %1;"
                             :: "l"(&g_epoch[mt][nt]), "r"((unsigned)(t + 1)) : "memory");
            }
        }
    }
}

// ---------------------------------------------------------------------------
// Phase 3: out[b][e] = sigmoid(hT[b][:] . W_fc[e][:] + b_fc[e]); h = hi + lo
// ---------------------------------------------------------------------------
__global__ void __launch_bounds__(128) fc_kernel(
    const float* __restrict__ Wfc, const float* __restrict__ bfc,
    float* __restrict__ out)
{
    __shared__ float hs[HH];
    const int b = blockIdx.x;
    const int tid = threadIdx.x;
    for (int k = tid; k < HH; k += 128)
        hs[k] = __bfloat162float(g_hhi[(size_t)b * HH + k]) +
                __bfloat162float(g_hlo[(size_t)b * HH + k]);
    __syncthreads();

    float acc = bfc[tid];
    const float* wp = Wfc + (size_t)tid * HH;
#pragma unroll 4
    for (int k = 0; k < HH; k += 4) {
        float4 w4 = *(const float4*)(wp + k);
        acc += hs[k] * w4.x + hs[k+1] * w4.y + hs[k+2] * w4.z + hs[k+3] * w4.w;
    }
    out[b * EE + tid] = sigf(acc);
}

// ---------------------------------------------------------------------------
extern "C" void kernel_launch(void* const* d_in, const int* in_sizes, int n_in,
                              void* d_out, int out_size) {
    const float* x   = (const float*)d_in[0];
    const float* h0  = (const float*)d_in[1];
    const float* c0  = (const float*)d_in[2];
    const float* Wih = (const float*)d_in[3];
    const float* Whh = (const float*)d_in[4];
    const float* bih = (const float*)d_in[5];
    const float* bhh = (const float*)d_in[6];
    const float* Wfc = (const float*)d_in[7];
    const float* bfc = (const float*)d_in[8];
    (void)in_sizes; (void)n_in; (void)out_size;

    cudaFuncSetAttribute(gx_kernel,   cudaFuncAttributeMaxDynamicSharedMemorySize, GX_SMEM);
    cudaFuncSetAttribute(lstm_kernel, cudaFuncAttributeMaxDynamicSharedMemorySize, LSTM_SMEM);

    void* pep = nullptr;
    cudaGetSymbolAddress(&pep, g_epoch);
    cudaMemsetAsync(pep, 0, sizeof(unsigned) * 4 * 32, 0);

    prep_kernel<<<G4, 256>>>(Whh, Wih, bih, bhh, h0);
    gx_kernel<<<dim3(32, 256), 256, GX_SMEM>>>(x);
    lstm_kernel<<<NREC, 256, LSTM_SMEM>>>(c0);
    fc_kernel<<<BB, EE>>>(Wfc, bfc, (float*)d_out);
}

// round 13
// speedup vs baseline: 1.3712x; 1.3712x over previous
#include <cuda_runtime.h>
#include <cuda_bf16.h>
#include <math.h>
#include <stdint.h>

// Problem dims
#define BB 256
#define TT 512
#define FF 256
#define HH 512
#define G4 2048
#define EE 128
#define NREC 128   // persistent CTAs (4 mt-groups x 32 nt)

// ---- device-global scratch (no allocations allowed) ----
__device__ float         g_gx[(size_t)TT * BB * G4];   // [T][B][4H] permuted input proj (+bias)
__device__ __nv_bfloat16 g_Wphi[(size_t)G4 * HH];      // permuted W_hh (bf16)
__device__ __nv_bfloat16 g_Wihphi[(size_t)G4 * FF];    // permuted W_ih (bf16)
__device__ float         g_biasp[G4];                  // permuted b_ih + b_hh
__device__ __nv_bfloat16 g_hhi[BB * HH];               // final h hi (for fc)
__device__ __nv_bfloat16 g_hlo[BB * HH];               // final h lo (for fc)
// h state in MMA A-fragment layout, double-buffered (WAR-safe under counter):
// [2][ (mt*4+wm)*32 + kc ][ lane ] -> uint4
__device__ uint4         g_hfrag[2][16384];
__device__ unsigned      g_count4[128];                // 4 barrier counters, 128B apart

// ---------------------------------------------------------------------------
// helpers
// ---------------------------------------------------------------------------
__device__ __forceinline__ uint32_t smem_u32(const void* p) {
    uint32_t a;
    asm("{ .reg .u64 t; cvta.to.shared.u64 t, %1; cvt.u32.u64 %0, t; }" : "=r"(a) : "l"(p));
    return a;
}
__device__ __forceinline__ float sigf(float x)   { return 1.f / (1.f + __expf(-x)); }
__device__ __forceinline__ float tanhfa(float x) { return 2.f / (1.f + __expf(-2.f * x)) - 1.f; }
__device__ __forceinline__ float tha(float x) {
    float y; asm("tanh.approx.f32 %0, %1;" : "=f"(y) : "f"(x)); return y;
}
__device__ __forceinline__ float sga(float x) { return fmaf(tha(0.5f * x), 0.5f, 0.5f); }

__device__ __forceinline__ uint32_t pack2hi(float a, float b) {
    __nv_bfloat162 h = __floats2bfloat162_rn(a, b);
    return reinterpret_cast<uint32_t&>(h);
}

__device__ __forceinline__ void ldsm4(uint32_t (&r)[4], uint32_t addr) {
    asm volatile("ldmatrix.sync.aligned.m8n8.x4.shared.b16 {%0,%1,%2,%3}, [%4];"
        : "=r"(r[0]), "=r"(r[1]), "=r"(r[2]), "=r"(r[3]) : "r"(addr));
}
__device__ __forceinline__ void mma16816(float (&c)[4], const uint32_t (&a)[4],
                                         const uint32_t b0, const uint32_t b1) {
    asm volatile("mma.sync.aligned.m16n8k16.row.col.f32.bf16.bf16.f32 "
        "{%0,%1,%2,%3}, {%4,%5,%6,%7}, {%8,%9}, {%0,%1,%2,%3};"
        : "+f"(c[0]), "+f"(c[1]), "+f"(c[2]), "+f"(c[3])
        : "r"(a[0]), "r"(a[1]), "r"(a[2]), "r"(a[3]), "r"(b0), "r"(b1));
}
__device__ __forceinline__ unsigned ldg_cg_u32(const unsigned* p) {
    unsigned v;
    asm volatile("ld.global.cg.u32 %0, [%1];" : "=r"(v) : "l"(p));
    return v;
}
__device__ __forceinline__ void lds128(uint4 &v, uint32_t addr) {
    asm volatile("ld.shared.v4.u32 {%0,%1,%2,%3}, [%4];"
        : "=r"(v.x), "=r"(v.y), "=r"(v.z), "=r"(v.w) : "r"(addr));
}

// ---------------------------------------------------------------------------
// 1-term MMA chunk: acc += A * W. NF n-fragments. (gx kernel)
// ---------------------------------------------------------------------------
template<int NF>
__device__ __forceinline__ void mma_chunk1g(
    const uint32_t aBase, const uint32_t wHi,
    const int wRowB, const int kw0, const int wm, const int wn, const int lane,
    float (&acc)[2][NF][4])
{
    const int la  = lane & 15;
    const int aKo = (lane & 16) ? 16 : 0;
    const int nB  = wn * (NF * 8) + (lane & 7) + ((lane & 16) ? 8 : 0);
    const int bKo = (lane & 8) ? 16 : 0;
    const int m0w = wm * 32;

#pragma unroll
    for (int kk = 0; kk < 4; kk++) {
        const int kb = kk * 32;
        uint32_t ah[2][4];
#pragma unroll
        for (int mf = 0; mf < 2; mf++) {
            int m = m0w + mf * 16 + la;
            uint32_t off = (uint32_t)(m * 128 + ((kb + aKo) ^ ((m & 7) << 4)));
            ldsm4(ah[mf], aBase + off);
        }
        uint32_t bh[NF][2];
#pragma unroll
        for (int nh = 0; nh < NF / 2; nh++) {
            int n = nB + nh * 16;
            uint32_t off = (uint32_t)(n * wRowB + ((kw0 + kb + bKo) ^ ((n & 7) << 4)));
            uint32_t r[4];
            ldsm4(r, wHi + off);
            bh[nh*2][0] = r[0]; bh[nh*2][1] = r[1];
            bh[nh*2+1][0] = r[2]; bh[nh*2+1][1] = r[3];
        }
#pragma unroll
        for (int mf = 0; mf < 2; mf++)
#pragma unroll
            for (int nf = 0; nf < NF; nf++)
                mma16816(acc[mf][nf], ah[mf], bh[nf][0], bh[nf][1]);
    }
}

// ---------------------------------------------------------------------------
// prep: permute W_hh/W_ih/bias to gate-interleaved columns (bf16).
// unit j, gate g: group=j/4, q=j%4 -> cols group*16 + {2q,2q+1,8+2q,9+2q}
// Also write h0 (bf16) into fragment-layout buffer 0.
// ---------------------------------------------------------------------------
__global__ void prep_kernel(const float* __restrict__ Whh, const float* __restrict__ Wih,
                            const float* __restrict__ bih, const float* __restrict__ bhh,
                            const float* __restrict__ h0)
{
    const int n = blockIdx.x;
    const int group = n >> 4, wi = n & 15;
    const int gate = ((wi >> 3) << 1) | (wi & 1);
    const int j = (group << 2) | ((wi & 7) >> 1);
    const int o = gate * HH + j;
    const int tid = threadIdx.x;

    {
        int k2 = tid * 2;
        uint32_t hi = pack2hi(Whh[(size_t)o * HH + k2], Whh[(size_t)o * HH + k2 + 1]);
        *(uint32_t*)&g_Wphi[(size_t)n * HH + k2] = hi;
    }
    if (tid < 128) {
        int k2 = tid * 2;
        uint32_t hi = pack2hi(Wih[(size_t)o * FF + k2], Wih[(size_t)o * FF + k2 + 1]);
        *(uint32_t*)&g_Wihphi[(size_t)n * FF + k2] = hi;
    }
    if (tid == 0) g_biasp[n] = bih[o] + bhh[o];
    if (n < BB) {   // h0 -> fragment layout (buffer 0)
        const int m = n;
        const int mt = m >> 6, mloc = m & 63, wm = mloc >> 4, row16 = mloc & 15;
        const int r8 = row16 & 7, aR = row16 >> 3;
#pragma unroll
        for (int e = 0; e < 2; e++) {
            int jd = tid * 2 + e;
            __nv_bfloat16 hi = __float2bfloat16(h0[(size_t)m * HH + jd]);
            int kc = jd >> 4, jc = jd & 15, p = (jc >> 1) & 3, aC = jc >> 3;
            size_t hw = ((size_t)((mt * 4 + wm) * 32 + kc) * 32 + (r8 * 4 + p)) * 8
                        + (aC * 2 + aR) * 2 + (jd & 1);
            ((__nv_bfloat16*)g_hfrag)[hw] = hi;
        }
    }
}

// ---------------------------------------------------------------------------
// Phase 1: gx = x @ Wihp^T + biasp (1-term bf16). Tile 128M x 64N, 4 iters.
// grid (32 nt, 256 mo). 8 warps: wm=w&3, wn=w>>2 (NF=4).
// smem: W 32KB @0 (rowB=512), A dbl-buf @32768 (2 x 16KB)
// ---------------------------------------------------------------------------
#define GX_SMEM 65536
__global__ void __launch_bounds__(256, 1) gx_kernel(const float* __restrict__ x)
{
    extern __shared__ char sm[];
    const uint32_t smu = smem_u32(sm);
    const int tid = threadIdx.x, w = tid >> 5, lane = tid & 31;
    const int wm = w & 3, wn = w >> 2;
    const int nt = blockIdx.x;
    const int n0 = nt * 64;
    const int q = lane & 3, r = lane >> 2;

    // resident W_ih (64 rows x 256 k, bf16): 2048 granules of 16B
#pragma unroll
    for (int i = 0; i < 8; i++) {
        int c = tid + i * 256;
        int n = c >> 5, g = c & 31;
        uint4 v = *(const uint4*)((const char*)g_Wihphi + (size_t)(n0 + n) * 512 + g * 16);
        *(uint4*)(sm + n * 512 + ((g * 16) ^ ((n & 7) << 4))) = v;
    }
    float2 bias2[4];
#pragma unroll
    for (int nf = 0; nf < 4; nf++)
        bias2[nf] = *(const float2*)&g_biasp[n0 + wn * 32 + nf * 8 + 2 * q];
    __syncthreads();

    uint4 shi[4];
#define GX_LD(kc, m0) do { \
    _Pragma("unroll") \
    for (int i2 = 0; i2 < 4; i2++) { \
        int c = tid + i2 * 256; int m = c >> 3, g = c & 7; \
        const float* sp = x + (size_t)((m0) + m) * FF + (kc) * 64 + g * 8; \
        float4 f0 = *(const float4*)sp; float4 f1 = *(const float4*)(sp + 4); \
        shi[i2].x = pack2hi(f0.x, f0.y); shi[i2].y = pack2hi(f0.z, f0.w); \
        shi[i2].z = pack2hi(f1.x, f1.y); shi[i2].w = pack2hi(f1.z, f1.w); \
    } } while (0)
#define GX_ST(buf) do { \
    _Pragma("unroll") \
    for (int i2 = 0; i2 < 4; i2++) { \
        int c = tid + i2 * 256; int m = c >> 3, g = c & 7; \
        *(uint4*)(sm + 32768 + (buf) * 16384 + m * 128 + ((g * 16) ^ ((m & 7) << 4))) = shi[i2]; \
    } } while (0)

    for (int it = 0; it < 4; it++) {
        const int m0 = blockIdx.y * 512 + it * 128;

        float acc[2][4][4];
#pragma unroll
        for (int a = 0; a < 2; a++)
#pragma unroll
            for (int b = 0; b < 4; b++)
#pragma unroll
                for (int cidx = 0; cidx < 4; cidx++) acc[a][b][cidx] = 0.f;

        GX_LD(0, m0); GX_ST(0); __syncthreads();
#pragma unroll
        for (int kc = 0; kc < 4; kc++) {
            if (kc < 3) GX_LD(kc + 1, m0);
            mma_chunk1g<4>(smu + 32768 + (kc & 1) * 16384, smu,
                           512, kc * 128, wm, wn, lane, acc);
            if (kc < 3) { GX_ST((kc + 1) & 1); __syncthreads(); }
        }

#pragma unroll
        for (int mf = 0; mf < 2; mf++)
#pragma unroll
            for (int rp = 0; rp < 2; rp++) {
                int m = m0 + wm * 32 + mf * 16 + r + rp * 8;
                int t = m & (TT - 1), b = m >> 9;
                float* dst = g_gx + ((size_t)t * BB + b) * G4;
#pragma unroll
                for (int nf = 0; nf < 4; nf++) {
                    int col = n0 + wn * 32 + nf * 8 + 2 * q;
                    *(float2*)(dst + col) =
                        make_float2(acc[mf][nf][rp*2+0] + bias2[nf].x,
                                    acc[mf][nf][rp*2+1] + bias2[nf].y);
                }
            }
        __syncthreads();
    }
}

// ---------------------------------------------------------------------------
// Phase 2: warp-autonomous persistent recurrent kernel (R10 base: R7 sync +
// pair-split cp.async exchange), with OWN-HALF-FIRST MMA ordering:
// warp wn MMAs its own 16 chunks right after its cp.async.wait_group (no
// barrier), then bar.sync(64) with partner, then partner's 16 chunks —
// hiding partner cp.async latency + barrier behind ~16 chunks of MMA.
// 128 CTAs x 256 thr; mt = bx&3, nt = bx>>2; 8 warps = 4 wm x 2 wn.
// smem: W 64KB @0; A 64KB @65536 (16KB/wm); pack scratch 2KB @131072.
// ---------------------------------------------------------------------------
#define LSTM_SMEM 133120
__global__ void __launch_bounds__(256, 1) lstm_kernel(const float* __restrict__ c0)
{
    extern __shared__ char sm[];
    const uint32_t smu = smem_u32(sm);
    const int tid = threadIdx.x, w = tid >> 5, lane = tid & 31;
    const int wm = w & 3, wn = w >> 2;
    const int bx = blockIdx.x;
    const int mt = bx & 3, nt = bx >> 2;
    const int m0 = mt * 64, n0 = nt * 64;
    const int q = lane & 3, r = lane >> 2;
    unsigned* cnt = &g_count4[mt * 32];

    // resident W (64 perm-cols x 512 k, bf16)
#pragma unroll
    for (int i = 0; i < 16; i++) {
        int c = tid + i * 256;
        int n = c >> 6, g = c & 63;
        uint4 v = *(const uint4*)((const char*)g_Wphi + (size_t)(n0 + n) * 1024 + g * 16);
        *(uint4*)(sm + n * 1024 + ((g * 16) ^ ((n & 7) << 4))) = v;
    }

    const int mr0 = m0 + wm * 16 + r;
    const int unitA = (nt * 4 + wn * 2) * 4 + q;
    const int unitB = unitA + 4;

    float creg[4];
    creg[0] = c0[(size_t)mr0 * HH + unitA];
    creg[1] = c0[(size_t)(mr0 + 8) * HH + unitA];
    creg[2] = c0[(size_t)mr0 * HH + unitB];
    creg[3] = c0[(size_t)(mr0 + 8) * HH + unitB];
    __syncthreads();    // W resident ready (only CTA-wide sync; outside the loop)

    // ldsm W addressing
    const int nW1 = wn * 32 + (lane & 7) + ((lane & 16) ? 8 : 0);
    const int nW2 = nW1 + 16;
    const int bKo = (lane & 8) ? 16 : 0;
    const uint32_t wb1 = smu + nW1 * 1024;
    const uint32_t wb2 = smu + nW2 * 1024;
    const int sw1 = (nW1 & 7) << 4, sw2 = (nW2 & 7) << 4;

    const int colA = n0 + wn * 32 + 2 * q;
    const int fragbase = ((mt * 4 + wm) * 32) * 32 + lane;
    const uint32_t aReg = smu + 65536 + (uint32_t)wm * 16384;   // per-wm A region
    const uint32_t aLane = aReg + (uint32_t)lane * 16;
    const uint32_t ps = smu + 131072 + w * 256;

    for (int t = 0; t < TT; t++) {
        // ---- gx loads (immutable; issued before the wait, overlap polling) ----
        const float* gp0 = g_gx + ((size_t)t * BB + mr0) * G4;
        const float* gp1 = gp0 + 8 * G4;
        float2 ifA0 = *(const float2*)(gp0 + colA);
        float2 goA0 = *(const float2*)(gp0 + colA + 8);
        float2 ifB0 = *(const float2*)(gp0 + colA + 16);
        float2 goB0 = *(const float2*)(gp0 + colA + 24);
        float2 ifA1 = *(const float2*)(gp1 + colA);
        float2 goA1 = *(const float2*)(gp1 + colA + 8);
        float2 ifB1 = *(const float2*)(gp1 + colA + 16);
        float2 goB1 = *(const float2*)(gp1 + colA + 24);

        // ---- per-warp wait on mt counter (R7) ----
        if (t) {
            const unsigned target = (unsigned)t * 256u;
            unsigned cur = ldg_cg_u32(cnt);
            while (cur < target) { __nanosleep(32); cur = ldg_cg_u32(cnt); }
        }
        __threadfence();   // acquire

        // ---- cp.async own 16 chunks into smem[wm] (L2-only path) ----
        const uint4* hin = &g_hfrag[t & 1][fragbase];
#pragma unroll
        for (int i = 0; i < 16; i++) {
            const int kc = wn * 16 + i;
            uint32_t dst = aReg + (uint32_t)(kc * 512 + lane * 16);
            const uint4* src = hin + kc * 32;
            asm volatile("cp.async.cg.shared.global [%0], [%1], 16;"
                         :: "r"(dst), "l"(src) : "memory");
        }
        asm volatile("cp.async.commit_group;" ::: "memory");
        asm volatile("cp.async.wait_group 0;" ::: "memory");
        // NOTE: no barrier yet — own data is self-produced, safe to consume.

        float acc[4][4];
#pragma unroll
        for (int a = 0; a < 4; a++)
#pragma unroll
            for (int cix = 0; cix < 4; cix++) acc[a][cix] = 0.f;

        // ---- half 1: OWN chunks (kc = wn*16 .. +15) ----
        {
            const int kb = wn * 16;
            uint4 ab[4];
#pragma unroll
            for (int i = 0; i < 4; i++) lds128(ab[i], aLane + (uint32_t)((kb + i) * 512));
#pragma unroll
            for (int i = 0; i < 16; i++) {
                const int kc = kb + i;
                uint32_t au[4] = { ab[i & 3].x, ab[i & 3].y, ab[i & 3].z, ab[i & 3].w };
                if (i < 12) lds128(ab[i & 3], aLane + (uint32_t)((kc + 4) * 512));
                uint32_t rA[4], rB[4];
                ldsm4(rA, wb1 + (uint32_t)((kc * 32 + bKo) ^ sw1));
                ldsm4(rB, wb2 + (uint32_t)((kc * 32 + bKo) ^ sw2));
                mma16816(acc[0], au, rA[0], rA[1]);
                mma16816(acc[1], au, rA[2], rA[3]);
                mma16816(acc[2], au, rB[0], rB[1]);
                mma16816(acc[3], au, rB[2], rB[3]);
            }
        }

        // ---- pair barrier: partner's cp.asyncs landed during our half 1 ----
        asm volatile("bar.sync %0, 64;" :: "r"(wm + 1) : "memory");

        // ---- half 2: PARTNER chunks (kc = (wn^1)*16 .. +15) ----
        {
            const int kb = (wn ^ 1) * 16;
            uint4 ab[4];
#pragma unroll
            for (int i = 0; i < 4; i++) lds128(ab[i], aLane + (uint32_t)((kb + i) * 512));
#pragma unroll
            for (int i = 0; i < 16; i++) {
                const int kc = kb + i;
                uint32_t au[4] = { ab[i & 3].x, ab[i & 3].y, ab[i & 3].z, ab[i & 3].w };
                if (i < 12) lds128(ab[i & 3], aLane + (uint32_t)((kc + 4) * 512));
                uint32_t rA[4], rB[4];
                ldsm4(rA, wb1 + (uint32_t)((kc * 32 + bKo) ^ sw1));
                ldsm4(rB, wb2 + (uint32_t)((kc * 32 + bKo) ^ sw2));
                mma16816(acc[0], au, rA[0], rA[1]);
                mma16816(acc[1], au, rA[2], rA[3]);
                mma16816(acc[2], au, rB[0], rB[1]);
                mma16816(acc[3], au, rB[2], rB[3]);
            }
        }

        // ---- epilogue: gates + state update (approx gates; exact last step) ----
        const bool last = (t == TT - 1);
        float hv[4];
        float sI[4], sF[4], sG[4], sO[4];
        sI[0] = acc[0][0] + ifA0.x;  sF[0] = acc[0][1] + ifA0.y;
        sG[0] = acc[1][0] + goA0.x;  sO[0] = acc[1][1] + goA0.y;
        sI[1] = acc[0][2] + ifA1.x;  sF[1] = acc[0][3] + ifA1.y;
        sG[1] = acc[1][2] + goA1.x;  sO[1] = acc[1][3] + goA1.y;
        sI[2] = acc[2][0] + ifB0.x;  sF[2] = acc[2][1] + ifB0.y;
        sG[2] = acc[3][0] + goB0.x;  sO[2] = acc[3][1] + goB0.y;
        sI[3] = acc[2][2] + ifB1.x;  sF[3] = acc[2][3] + ifB1.y;
        sG[3] = acc[3][2] + goB1.x;  sO[3] = acc[3][3] + goB1.y;
#pragma unroll
        for (int cell = 0; cell < 4; cell++) {
            float iv, fv, gv, ov, cc;
            if (!last) {
                iv = sga(sI[cell]); fv = sga(sF[cell]);
                gv = tha(sG[cell]); ov = sga(sO[cell]);
                cc = fv * creg[cell] + iv * gv;
                hv[cell] = ov * tha(cc);
            } else {
                iv = sigf(sI[cell]); fv = sigf(sF[cell]);
                gv = tanhfa(sG[cell]); ov = sigf(sO[cell]);
                cc = fv * creg[cell] + iv * gv;
                hv[cell] = ov * tanhfa(cc);
            }
            creg[cell] = cc;
        }

        // ---- pack h into A-fragment words (warp-local smem), publish ----
#pragma unroll
        for (int cell = 0; cell < 4; cell++) {
            int rp = cell & 1, g = cell >> 1;
            unsigned short hb;
            __nv_bfloat16 b16 = __float2bfloat16(hv[cell]);
            hb = *(unsigned short*)&b16;
            uint32_t addr = ps + (uint32_t)((r + rp * 8) * 16 + (g * 4 + q) * 2);
            asm volatile("st.shared.u16 [%0], %1;" :: "r"(addr), "h"(hb));
        }
        __syncwarp();
        {
            uint32_t v0, v1;
            asm volatile("ld.shared.u32 %0, [%1];" : "=r"(v0)
                         : "r"(ps + (uint32_t)((lane >> 2) * 16 + (lane & 3) * 4)));
            asm volatile("ld.shared.u32 %0, [%1];" : "=r"(v1)
                         : "r"(ps + (uint32_t)(((lane >> 2) + 8) * 16 + (lane & 3) * 4)));
            uint2 outw = make_uint2(v0, v1);
            uint2* hop = (uint2*)&g_hfrag[(t + 1) & 1][((mt * 4 + wm) * 32 + nt) * 32];
            hop[lane * 2 + wn] = outw;
        }

        if (last) {   // also publish original-layout h (hi+lo) for fc
#pragma unroll
            for (int cell = 0; cell < 4; cell++) {
                int rp = cell & 1, g = cell >> 1;
                int m = mr0 + rp * 8;
                int u = g ? unitB : unitA;
                __nv_bfloat16 hi = __float2bfloat16(hv[cell]);
                g_hhi[(size_t)m * HH + u] = hi;
                g_hlo[(size_t)m * HH + u] = __float2bfloat16(hv[cell] - __bfloat162float(hi));
            }
        }

        // ---- per-warp release + arrive (R7) ----
        __threadfence();
        if (lane == 0) atomicAdd(cnt, 1u);
    }
}

// ---------------------------------------------------------------------------
// Phase 3: out[b][e] = sigmoid(hT[b][:] . W_fc[e][:] + b_fc[e]); h = hi + lo
// ---------------------------------------------------------------------------
__global__ void __launch_bounds__(128) fc_kernel(
    const float* __restrict__ Wfc, const float* __restrict__ bfc,
    float* __restrict__ out)
{
    __shared__ float hs[HH];
    const int b = blockIdx.x;
    const int tid = threadIdx.x;
    for (int k = tid; k < HH; k += 128)
        hs[k] = __bfloat162float(g_hhi[(size_t)b * HH + k]) +
                __bfloat162float(g_hlo[(size_t)b * HH + k]);
    __syncthreads();

    float acc = bfc[tid];
    const float* wp = Wfc + (size_t)tid * HH;
#pragma unroll 4
    for (int k = 0; k < HH; k += 4) {
        float4 w4 = *(const float4*)(wp + k);
        acc += hs[k] * w4.x + hs[k+1] * w4.y + hs[k+2] * w4.z + hs[k+3] * w4.w;
    }
    out[b * EE + tid] = sigf(acc);
}

// ---------------------------------------------------------------------------
extern "C" void kernel_launch(void* const* d_in, const int* in_sizes, int n_in,
                              void* d_out, int out_size) {
    const float* x   = (const float*)d_in[0];
    const float* h0  = (const float*)d_in[1];
    const float* c0  = (const float*)d_in[2];
    const float* Wih = (const float*)d_in[3];
    const float* Whh = (const float*)d_in[4];
    const float* bih = (const float*)d_in[5];
    const float* bhh = (const float*)d_in[6];
    const float* Wfc = (const float*)d_in[7];
    const float* bfc = (const float*)d_in[8];
    (void)in_sizes; (void)n_in; (void)out_size;

    cudaFuncSetAttribute(gx_kernel,   cudaFuncAttributeMaxDynamicSharedMemorySize, GX_SMEM);
    cudaFuncSetAttribute(lstm_kernel, cudaFuncAttributeMaxDynamicSharedMemorySize, LSTM_SMEM);

    void* pcount = nullptr;
    cudaGetSymbolAddress(&pcount, g_count4);
    cudaMemsetAsync(pcount, 0, 128 * sizeof(unsigned), 0);

    prep_kernel<<<G4, 256>>>(Whh, Wih, bih, bhh, h0);
    gx_kernel<<<dim3(32, 256), 256, GX_SMEM>>>(x);
    lstm_kernel<<<NREC, 256, LSTM_SMEM>>>(c0);
    fc_kernel<<<BB, EE>>>(Wfc, bfc, (float*)d_out);
}

// round 14
// speedup vs baseline: 1.4918x; 1.0880x over previous
#include <cuda_runtime.h>
#include <cuda_bf16.h>
#include <math.h>
#include <stdint.h>

// Problem dims
#define BB 256
#define TT 512
#define FF 256
#define HH 512
#define G4 2048
#define EE 128
#define NREC 128   // persistent CTAs (4 mt-groups x 32 nt)

// ---- device-global scratch (no allocations allowed) ----
__device__ float         g_gx[(size_t)TT * BB * G4];   // [T][B][4H] permuted input proj (+bias)
__device__ __nv_bfloat16 g_Wphi[(size_t)G4 * HH];      // permuted W_hh (bf16)
__device__ __nv_bfloat16 g_Wihphi[(size_t)G4 * FF];    // permuted W_ih (bf16)
__device__ float         g_biasp[G4];                  // permuted b_ih + b_hh
__device__ __nv_bfloat16 g_hhi[BB * HH];               // final h hi (for fc)
__device__ __nv_bfloat16 g_hlo[BB * HH];               // final h lo (for fc)
// h state in MMA A-fragment layout, TRIPLE-buffered (WAR-safe under split
// counters, see header comment in lstm_kernel):
// [3][ (mt*4+wm)*32 + kc ][ lane ] -> uint4
__device__ uint4         g_hfrag[3][16384];
// per-mt split counters: [mt*32 + 0] = arrivals from CTAs nt<16 (half A),
//                        [mt*32 + 16] = arrivals from CTAs nt>=16 (half B)
__device__ unsigned      g_count4[128];

// ---------------------------------------------------------------------------
// helpers
// ---------------------------------------------------------------------------
__device__ __forceinline__ uint32_t smem_u32(const void* p) {
    uint32_t a;
    asm("{ .reg .u64 t; cvta.to.shared.u64 t, %1; cvt.u32.u64 %0, t; }" : "=r"(a) : "l"(p));
    return a;
}
__device__ __forceinline__ float sigf(float x)   { return 1.f / (1.f + __expf(-x)); }
__device__ __forceinline__ float tanhfa(float x) { return 2.f / (1.f + __expf(-2.f * x)) - 1.f; }
__device__ __forceinline__ float tha(float x) {
    float y; asm("tanh.approx.f32 %0, %1;" : "=f"(y) : "f"(x)); return y;
}
__device__ __forceinline__ float sga(float x) { return fmaf(tha(0.5f * x), 0.5f, 0.5f); }

__device__ __forceinline__ uint32_t pack2hi(float a, float b) {
    __nv_bfloat162 h = __floats2bfloat162_rn(a, b);
    return reinterpret_cast<uint32_t&>(h);
}

__device__ __forceinline__ void ldsm4(uint32_t (&r)[4], uint32_t addr) {
    asm volatile("ldmatrix.sync.aligned.m8n8.x4.shared.b16 {%0,%1,%2,%3}, [%4];"
        : "=r"(r[0]), "=r"(r[1]), "=r"(r[2]), "=r"(r[3]) : "r"(addr));
}
__device__ __forceinline__ void mma16816(float (&c)[4], const uint32_t (&a)[4],
                                         const uint32_t b0, const uint32_t b1) {
    asm volatile("mma.sync.aligned.m16n8k16.row.col.f32.bf16.bf16.f32 "
        "{%0,%1,%2,%3}, {%4,%5,%6,%7}, {%8,%9}, {%0,%1,%2,%3};"
        : "+f"(c[0]), "+f"(c[1]), "+f"(c[2]), "+f"(c[3])
        : "r"(a[0]), "r"(a[1]), "r"(a[2]), "r"(a[3]), "r"(b0), "r"(b1));
}
__device__ __forceinline__ unsigned ldg_cg_u32(const unsigned* p) {
    unsigned v;
    asm volatile("ld.global.cg.u32 %0, [%1];" : "=r"(v) : "l"(p));
    return v;
}
__device__ __forceinline__ void lds128(uint4 &v, uint32_t addr) {
    asm volatile("ld.shared.v4.u32 {%0,%1,%2,%3}, [%4];"
        : "=r"(v.x), "=r"(v.y), "=r"(v.z), "=r"(v.w) : "r"(addr));
}

// ---------------------------------------------------------------------------
// 1-term MMA chunk: acc += A * W. NF n-fragments. (gx kernel)
// ---------------------------------------------------------------------------
template<int NF>
__device__ __forceinline__ void mma_chunk1g(
    const uint32_t aBase, const uint32_t wHi,
    const int wRowB, const int kw0, const int wm, const int wn, const int lane,
    float (&acc)[2][NF][4])
{
    const int la  = lane & 15;
    const int aKo = (lane & 16) ? 16 : 0;
    const int nB  = wn * (NF * 8) + (lane & 7) + ((lane & 16) ? 8 : 0);
    const int bKo = (lane & 8) ? 16 : 0;
    const int m0w = wm * 32;

#pragma unroll
    for (int kk = 0; kk < 4; kk++) {
        const int kb = kk * 32;
        uint32_t ah[2][4];
#pragma unroll
        for (int mf = 0; mf < 2; mf++) {
            int m = m0w + mf * 16 + la;
            uint32_t off = (uint32_t)(m * 128 + ((kb + aKo) ^ ((m & 7) << 4)));
            ldsm4(ah[mf], aBase + off);
        }
        uint32_t bh[NF][2];
#pragma unroll
        for (int nh = 0; nh < NF / 2; nh++) {
            int n = nB + nh * 16;
            uint32_t off = (uint32_t)(n * wRowB + ((kw0 + kb + bKo) ^ ((n & 7) << 4)));
            uint32_t r[4];
            ldsm4(r, wHi + off);
            bh[nh*2][0] = r[0]; bh[nh*2][1] = r[1];
            bh[nh*2+1][0] = r[2]; bh[nh*2+1][1] = r[3];
        }
#pragma unroll
        for (int mf = 0; mf < 2; mf++)
#pragma unroll
            for (int nf = 0; nf < NF; nf++)
                mma16816(acc[mf][nf], ah[mf], bh[nf][0], bh[nf][1]);
    }
}

// ---------------------------------------------------------------------------
// prep: permute W_hh/W_ih/bias to gate-interleaved columns (bf16).
// unit j, gate g: group=j/4, q=j%4 -> cols group*16 + {2q,2q+1,8+2q,9+2q}
// Also write h0 (bf16) into fragment-layout buffer 0.
// ---------------------------------------------------------------------------
__global__ void prep_kernel(const float* __restrict__ Whh, const float* __restrict__ Wih,
                            const float* __restrict__ bih, const float* __restrict__ bhh,
                            const float* __restrict__ h0)
{
    const int n = blockIdx.x;
    const int group = n >> 4, wi = n & 15;
    const int gate = ((wi >> 3) << 1) | (wi & 1);
    const int j = (group << 2) | ((wi & 7) >> 1);
    const int o = gate * HH + j;
    const int tid = threadIdx.x;

    {
        int k2 = tid * 2;
        uint32_t hi = pack2hi(Whh[(size_t)o * HH + k2], Whh[(size_t)o * HH + k2 + 1]);
        *(uint32_t*)&g_Wphi[(size_t)n * HH + k2] = hi;
    }
    if (tid < 128) {
        int k2 = tid * 2;
        uint32_t hi = pack2hi(Wih[(size_t)o * FF + k2], Wih[(size_t)o * FF + k2 + 1]);
        *(uint32_t*)&g_Wihphi[(size_t)n * FF + k2] = hi;
    }
    if (tid == 0) g_biasp[n] = bih[o] + bhh[o];
    if (n < BB) {   // h0 -> fragment layout (buffer 0)
        const int m = n;
        const int mt = m >> 6, mloc = m & 63, wm = mloc >> 4, row16 = mloc & 15;
        const int r8 = row16 & 7, aR = row16 >> 3;
#pragma unroll
        for (int e = 0; e < 2; e++) {
            int jd = tid * 2 + e;
            __nv_bfloat16 hi = __float2bfloat16(h0[(size_t)m * HH + jd]);
            int kc = jd >> 4, jc = jd & 15, p = (jc >> 1) & 3, aC = jc >> 3;
            size_t hw = ((size_t)((mt * 4 + wm) * 32 + kc) * 32 + (r8 * 4 + p)) * 8
                        + (aC * 2 + aR) * 2 + (jd & 1);
            ((__nv_bfloat16*)g_hfrag)[hw] = hi;
        }
    }
}

// ---------------------------------------------------------------------------
// Phase 1: gx = x @ Wihp^T + biasp (1-term bf16). Tile 128M x 64N, 4 iters.
// grid (32 nt, 256 mo). 8 warps: wm=w&3, wn=w>>2 (NF=4).
// smem: W 32KB @0 (rowB=512), A dbl-buf @32768 (2 x 16KB)
// ---------------------------------------------------------------------------
#define GX_SMEM 65536
__global__ void __launch_bounds__(256, 1) gx_kernel(const float* __restrict__ x)
{
    extern __shared__ char sm[];
    const uint32_t smu = smem_u32(sm);
    const int tid = threadIdx.x, w = tid >> 5, lane = tid & 31;
    const int wm = w & 3, wn = w >> 2;
    const int nt = blockIdx.x;
    const int n0 = nt * 64;
    const int q = lane & 3, r = lane >> 2;

    // resident W_ih (64 rows x 256 k, bf16): 2048 granules of 16B
#pragma unroll
    for (int i = 0; i < 8; i++) {
        int c = tid + i * 256;
        int n = c >> 5, g = c & 31;
        uint4 v = *(const uint4*)((const char*)g_Wihphi + (size_t)(n0 + n) * 512 + g * 16);
        *(uint4*)(sm + n * 512 + ((g * 16) ^ ((n & 7) << 4))) = v;
    }
    float2 bias2[4];
#pragma unroll
    for (int nf = 0; nf < 4; nf++)
        bias2[nf] = *(const float2*)&g_biasp[n0 + wn * 32 + nf * 8 + 2 * q];
    __syncthreads();

    uint4 shi[4];
#define GX_LD(kc, m0) do { \
    _Pragma("unroll") \
    for (int i2 = 0; i2 < 4; i2++) { \
        int c = tid + i2 * 256; int m = c >> 3, g = c & 7; \
        const float* sp = x + (size_t)((m0) + m) * FF + (kc) * 64 + g * 8; \
        float4 f0 = *(const float4*)sp; float4 f1 = *(const float4*)(sp + 4); \
        shi[i2].x = pack2hi(f0.x, f0.y); shi[i2].y = pack2hi(f0.z, f0.w); \
        shi[i2].z = pack2hi(f1.x, f1.y); shi[i2].w = pack2hi(f1.z, f1.w); \
    } } while (0)
#define GX_ST(buf) do { \
    _Pragma("unroll") \
    for (int i2 = 0; i2 < 4; i2++) { \
        int c = tid + i2 * 256; int m = c >> 3, g = c & 7; \
        *(uint4*)(sm + 32768 + (buf) * 16384 + m * 128 + ((g * 16) ^ ((m & 7) << 4))) = shi[i2]; \
    } } while (0)

    for (int it = 0; it < 4; it++) {
        const int m0 = blockIdx.y * 512 + it * 128;

        float acc[2][4][4];
#pragma unroll
        for (int a = 0; a < 2; a++)
#pragma unroll
            for (int b = 0; b < 4; b++)
#pragma unroll
                for (int cidx = 0; cidx < 4; cidx++) acc[a][b][cidx] = 0.f;

        GX_LD(0, m0); GX_ST(0); __syncthreads();
#pragma unroll
        for (int kc = 0; kc < 4; kc++) {
            if (kc < 3) GX_LD(kc + 1, m0);
            mma_chunk1g<4>(smu + 32768 + (kc & 1) * 16384, smu,
                           512, kc * 128, wm, wn, lane, acc);
            if (kc < 3) { GX_ST((kc + 1) & 1); __syncthreads(); }
        }

#pragma unroll
        for (int mf = 0; mf < 2; mf++)
#pragma unroll
            for (int rp = 0; rp < 2; rp++) {
                int m = m0 + wm * 32 + mf * 16 + r + rp * 8;
                int t = m & (TT - 1), b = m >> 9;
                float* dst = g_gx + ((size_t)t * BB + b) * G4;
#pragma unroll
                for (int nf = 0; nf < 4; nf++) {
                    int col = n0 + wn * 32 + nf * 8 + 2 * q;
                    *(float2*)(dst + col) =
                        make_float2(acc[mf][nf][rp*2+0] + bias2[nf].x,
                                    acc[mf][nf][rp*2+1] + bias2[nf].y);
                }
            }
        __syncthreads();
    }
}

// ---------------------------------------------------------------------------
// Phase 2: warp-autonomous persistent recurrent kernel.
// R13 base (pair-split cp.async exchange, own-half-first MMA) with SPLIT
// per-mt counters: cntA counts arrivals from CTAs nt<16 (producers of
// chunks 0..15), cntB from nt>=16 (chunks 16..31). Warp wn waits ONLY the
// counter for the half it loads; bar.sync(64) joins the pair before the
// partner-half MMA. Triple-buffered h frags: writer at step t (buffer
// (t+1)%3) races readers at t-2; writer passed half-cnt >= t*128 => its
// half finished t-1 => (their partners' step t-1 half-waits) other half
// finished t-2. Safe. Reader-side __threadfence dropped: all exchange is
// .cg/cp.async (L2 = coherence point) and per-warp in-order issue orders
// poll -> cp.async; producer-side fence retained.
// 128 CTAs x 256 thr; mt = bx&3, nt = bx>>2; 8 warps = 4 wm x 2 wn.
// smem: W 64KB @0; A 64KB @65536 (16KB/wm); pack scratch 2KB @131072.
// ---------------------------------------------------------------------------
#define LSTM_SMEM 133120
__global__ void __launch_bounds__(256, 1) lstm_kernel(const float* __restrict__ c0)
{
    extern __shared__ char sm[];
    const uint32_t smu = smem_u32(sm);
    const int tid = threadIdx.x, w = tid >> 5, lane = tid & 31;
    const int wm = w & 3, wn = w >> 2;
    const int bx = blockIdx.x;
    const int mt = bx & 3, nt = bx >> 2;
    const int m0 = mt * 64, n0 = nt * 64;
    const int q = lane & 3, r = lane >> 2;
    unsigned* cntWait = &g_count4[mt * 32 + (wn ? 16 : 0)];       // half I load
    unsigned* cntMine = &g_count4[mt * 32 + (nt >= 16 ? 16 : 0)]; // half I produce

    // resident W (64 perm-cols x 512 k, bf16)
#pragma unroll
    for (int i = 0; i < 16; i++) {
        int c = tid + i * 256;
        int n = c >> 6, g = c & 63;
        uint4 v = *(const uint4*)((const char*)g_Wphi + (size_t)(n0 + n) * 1024 + g * 16);
        *(uint4*)(sm + n * 1024 + ((g * 16) ^ ((n & 7) << 4))) = v;
    }

    const int mr0 = m0 + wm * 16 + r;
    const int unitA = (nt * 4 + wn * 2) * 4 + q;
    const int unitB = unitA + 4;

    float creg[4];
    creg[0] = c0[(size_t)mr0 * HH + unitA];
    creg[1] = c0[(size_t)(mr0 + 8) * HH + unitA];
    creg[2] = c0[(size_t)mr0 * HH + unitB];
    creg[3] = c0[(size_t)(mr0 + 8) * HH + unitB];
    __syncthreads();    // W resident ready (only CTA-wide sync; outside the loop)

    // ldsm W addressing
    const int nW1 = wn * 32 + (lane & 7) + ((lane & 16) ? 8 : 0);
    const int nW2 = nW1 + 16;
    const int bKo = (lane & 8) ? 16 : 0;
    const uint32_t wb1 = smu + nW1 * 1024;
    const uint32_t wb2 = smu + nW2 * 1024;
    const int sw1 = (nW1 & 7) << 4, sw2 = (nW2 & 7) << 4;

    const int colA = n0 + wn * 32 + 2 * q;
    const int fragbase = ((mt * 4 + wm) * 32) * 32 + lane;
    const uint32_t aReg = smu + 65536 + (uint32_t)wm * 16384;   // per-wm A region
    const uint32_t aLane = aReg + (uint32_t)lane * 16;
    const uint32_t ps = smu + 131072 + w * 256;

    int br = 0;   // t % 3

    for (int t = 0; t < TT; t++) {
        // ---- gx loads (immutable; issued before the wait, overlap polling) ----
        const float* gp0 = g_gx + ((size_t)t * BB + mr0) * G4;
        const float* gp1 = gp0 + 8 * G4;
        float2 ifA0 = *(const float2*)(gp0 + colA);
        float2 goA0 = *(const float2*)(gp0 + colA + 8);
        float2 ifB0 = *(const float2*)(gp0 + colA + 16);
        float2 goB0 = *(const float2*)(gp0 + colA + 24);
        float2 ifA1 = *(const float2*)(gp1 + colA);
        float2 goA1 = *(const float2*)(gp1 + colA + 8);
        float2 ifB1 = *(const float2*)(gp1 + colA + 16);
        float2 goB1 = *(const float2*)(gp1 + colA + 24);

        // ---- per-warp wait: ONLY my half's producers (fan-in 128) ----
        if (t) {
            const unsigned target = (unsigned)t * 128u;
            unsigned cur = ldg_cg_u32(cntWait);
            while (cur < target) { __nanosleep(32); cur = ldg_cg_u32(cntWait); }
        }
        // (no reader fence: .cg/cp.async are L2-coherent; in-order issue)

        // ---- cp.async own 16 chunks into smem[wm] (L2-only path) ----
        const uint4* hin = &g_hfrag[br][fragbase];
#pragma unroll
        for (int i = 0; i < 16; i++) {
            const int kc = wn * 16 + i;
            uint32_t dst = aReg + (uint32_t)(kc * 512 + lane * 16);
            const uint4* src = hin + kc * 32;
            asm volatile("cp.async.cg.shared.global [%0], [%1], 16;"
                         :: "r"(dst), "l"(src) : "memory");
        }
        asm volatile("cp.async.commit_group;" ::: "memory");
        asm volatile("cp.async.wait_group 0;" ::: "memory");

        float acc[4][4];
#pragma unroll
        for (int a = 0; a < 4; a++)
#pragma unroll
            for (int cix = 0; cix < 4; cix++) acc[a][cix] = 0.f;

        // ---- half 1: OWN chunks (kc = wn*16 .. +15) ----
        {
            const int kb = wn * 16;
            uint4 ab[4];
#pragma unroll
            for (int i = 0; i < 4; i++) lds128(ab[i], aLane + (uint32_t)((kb + i) * 512));
#pragma unroll
            for (int i = 0; i < 16; i++) {
                const int kc = kb + i;
                uint32_t au[4] = { ab[i & 3].x, ab[i & 3].y, ab[i & 3].z, ab[i & 3].w };
                if (i < 12) lds128(ab[i & 3], aLane + (uint32_t)((kc + 4) * 512));
                uint32_t rA[4], rB[4];
                ldsm4(rA, wb1 + (uint32_t)((kc * 32 + bKo) ^ sw1));
                ldsm4(rB, wb2 + (uint32_t)((kc * 32 + bKo) ^ sw2));
                mma16816(acc[0], au, rA[0], rA[1]);
                mma16816(acc[1], au, rA[2], rA[3]);
                mma16816(acc[2], au, rB[0], rB[1]);
                mma16816(acc[3], au, rB[2], rB[3]);
            }
        }

        // ---- pair barrier: partner's half landed during our half 1 ----
        asm volatile("bar.sync %0, 64;" :: "r"(wm + 1) : "memory");

        // ---- half 2: PARTNER chunks (kc = (wn^1)*16 .. +15) ----
        {
            const int kb = (wn ^ 1) * 16;
            uint4 ab[4];
#pragma unroll
            for (int i = 0; i < 4; i++) lds128(ab[i], aLane + (uint32_t)((kb + i) * 512));
#pragma unroll
            for (int i = 0; i < 16; i++) {
                const int kc = kb + i;
                uint32_t au[4] = { ab[i & 3].x, ab[i & 3].y, ab[i & 3].z, ab[i & 3].w };
                if (i < 12) lds128(ab[i & 3], aLane + (uint32_t)((kc + 4) * 512));
                uint32_t rA[4], rB[4];
                ldsm4(rA, wb1 + (uint32_t)((kc * 32 + bKo) ^ sw1));
                ldsm4(rB, wb2 + (uint32_t)((kc * 32 + bKo) ^ sw2));
                mma16816(acc[0], au, rA[0], rA[1]);
                mma16816(acc[1], au, rA[2], rA[3]);
                mma16816(acc[2], au, rB[0], rB[1]);
                mma16816(acc[3], au, rB[2], rB[3]);
            }
        }

        // ---- epilogue: gates + state update (approx gates; exact last step) ----
        const bool last = (t == TT - 1);
        float hv[4];
        float sI[4], sF[4], sG[4], sO[4];
        sI[0] = acc[0][0] + ifA0.x;  sF[0] = acc[0][1] + ifA0.y;
        sG[0] = acc[1][0] + goA0.x;  sO[0] = acc[1][1] + goA0.y;
        sI[1] = acc[0][2] + ifA1.x;  sF[1] = acc[0][3] + ifA1.y;
        sG[1] = acc[1][2] + goA1.x;  sO[1] = acc[1][3] + goA1.y;
        sI[2] = acc[2][0] + ifB0.x;  sF[2] = acc[2][1] + ifB0.y;
        sG[2] = acc[3][0] + goB0.x;  sO[2] = acc[3][1] + goB0.y;
        sI[3] = acc[2][2] + ifB1.x;  sF[3] = acc[2][3] + ifB1.y;
        sG[3] = acc[3][2] + goB1.x;  sO[3] = acc[3][3] + goB1.y;
#pragma unroll
        for (int cell = 0; cell < 4; cell++) {
            float iv, fv, gv, ov, cc;
            if (!last) {
                iv = sga(sI[cell]); fv = sga(sF[cell]);
                gv = tha(sG[cell]); ov = sga(sO[cell]);
                cc = fv * creg[cell] + iv * gv;
                hv[cell] = ov * tha(cc);
            } else {
                iv = sigf(sI[cell]); fv = sigf(sF[cell]);
                gv = tanhfa(sG[cell]); ov = sigf(sO[cell]);
                cc = fv * creg[cell] + iv * gv;
                hv[cell] = ov * tanhfa(cc);
            }
            creg[cell] = cc;
        }

        // ---- pack h into A-fragment words (warp-local smem), publish ----
#pragma unroll
        for (int cell = 0; cell < 4; cell++) {
            int rp = cell & 1, g = cell >> 1;
            unsigned short hb;
            __nv_bfloat16 b16 = __float2bfloat16(hv[cell]);
            hb = *(unsigned short*)&b16;
            uint32_t addr = ps + (uint32_t)((r + rp * 8) * 16 + (g * 4 + q) * 2);
            asm volatile("st.shared.u16 [%0], %1;" :: "r"(addr), "h"(hb));
        }
        __syncwarp();
        const int bw = (br + 1 == 3) ? 0 : br + 1;
        {
            uint32_t v0, v1;
            asm volatile("ld.shared.u32 %0, [%1];" : "=r"(v0)
                         : "r"(ps + (uint32_t)((lane >> 2) * 16 + (lane & 3) * 4)));
            asm volatile("ld.shared.u32 %0, [%1];" : "=r"(v1)
                         : "r"(ps + (uint32_t)(((lane >> 2) + 8) * 16 + (lane & 3) * 4)));
            uint2 outw = make_uint2(v0, v1);
            uint2* hop = (uint2*)&g_hfrag[bw][((mt * 4 + wm) * 32 + nt) * 32];
            hop[lane * 2 + wn] = outw;
        }

        if (last) {   // also publish original-layout h (hi+lo) for fc
#pragma unroll
            for (int cell = 0; cell < 4; cell++) {
                int rp = cell & 1, g = cell >> 1;
                int m = mr0 + rp * 8;
                int u = g ? unitB : unitA;
                __nv_bfloat16 hi = __float2bfloat16(hv[cell]);
                g_hhi[(size_t)m * HH + u] = hi;
                g_hlo[(size_t)m * HH + u] = __float2bfloat16(hv[cell] - __bfloat162float(hi));
            }
        }

        // ---- per-warp release + arrive on MY half's counter ----
        __threadfence();
        if (lane == 0) atomicAdd(cntMine, 1u);
        br = bw;
    }
}

// ---------------------------------------------------------------------------
// Phase 3: out[b][e] = sigmoid(hT[b][:] . W_fc[e][:] + b_fc[e]); h = hi + lo
// ---------------------------------------------------------------------------
__global__ void __launch_bounds__(128) fc_kernel(
    const float* __restrict__ Wfc, const float* __restrict__ bfc,
    float* __restrict__ out)
{
    __shared__ float hs[HH];
    const int b = blockIdx.x;
    const int tid = threadIdx.x;
    for (int k = tid; k < HH; k += 128)
        hs[k] = __bfloat162float(g_hhi[(size_t)b * HH + k]) +
                __bfloat162float(g_hlo[(size_t)b * HH + k]);
    __syncthreads();

    float acc = bfc[tid];
    const float* wp = Wfc + (size_t)tid * HH;
#pragma unroll 4
    for (int k = 0; k < HH; k += 4) {
        float4 w4 = *(const float4*)(wp + k);
        acc += hs[k] * w4.x + hs[k+1] * w4.y + hs[k+2] * w4.z + hs[k+3] * w4.w;
    }
    out[b * EE + tid] = sigf(acc);
}

// ---------------------------------------------------------------------------
extern "C" void kernel_launch(void* const* d_in, const int* in_sizes, int n_in,
                              void* d_out, int out_size) {
    const float* x   = (const float*)d_in[0];
    const float* h0  = (const float*)d_in[1];
    const float* c0  = (const float*)d_in[2];
    const float* Wih = (const float*)d_in[3];
    const float* Whh = (const float*)d_in[4];
    const float* bih = (const float*)d_in[5];
    const float* bhh = (const float*)d_in[6];
    const float* Wfc = (const float*)d_in[7];
    const float* bfc = (const float*)d_in[8];
    (void)in_sizes; (void)n_in; (void)out_size;

    cudaFuncSetAttribute(gx_kernel,   cudaFuncAttributeMaxDynamicSharedMemorySize, GX_SMEM);
    cudaFuncSetAttribute(lstm_kernel, cudaFuncAttributeMaxDynamicSharedMemorySize, LSTM_SMEM);

    void* pcount = nullptr;
    cudaGetSymbolAddress(&pcount, g_count4);
    cudaMemsetAsync(pcount, 0, 128 * sizeof(unsigned), 0);

    prep_kernel<<<G4, 256>>>(Whh, Wih, bih, bhh, h0);
    gx_kernel<<<dim3(32, 256), 256, GX_SMEM>>>(x);
    lstm_kernel<<<NREC, 256, LSTM_SMEM>>>(c0);
    fc_kernel<<<BB, EE>>>(Wfc, bfc, (float*)d_out);
}

// round 15
// speedup vs baseline: 1.5533x; 1.0412x over previous
#include <cuda_runtime.h>
#include <cuda_bf16.h>
#include <math.h>
#include <stdint.h>

// Problem dims
#define BB 256
#define TT 512
#define FF 256
#define HH 512
#define G4 2048
#define EE 128
#define NREC 128   // persistent CTAs (4 mt-groups x 32 nt)

// ---- device-global scratch (no allocations allowed) ----
__device__ float         g_gx[(size_t)TT * BB * G4];   // [T][B][4H] permuted input proj (+bias)
__device__ __nv_bfloat16 g_Wphi[(size_t)G4 * HH];      // permuted W_hh (bf16)
__device__ __nv_bfloat16 g_Wihphi[(size_t)G4 * FF];    // permuted W_ih (bf16)
__device__ float         g_biasp[G4];                  // permuted b_ih + b_hh
__device__ __nv_bfloat16 g_hhi[BB * HH];               // final h hi (for fc)
__device__ __nv_bfloat16 g_hlo[BB * HH];               // final h lo (for fc)
// h state in MMA A-fragment layout, TRIPLE-buffered (WAR-safe, see lstm hdr):
// [3][ (mt*4+wm)*32 + kc ][ lane ] -> uint4
__device__ uint4         g_hfrag[3][16384];
// per-(mt, quarter) counters, each on its own 128B line:
// index (mt*4 + qu)*32 ; qu = nt>>3 ; 64 arrivals (8 CTAs x 8 warps) per step
__device__ __align__(128) unsigned g_cntq[4 * 4 * 32];

// ---------------------------------------------------------------------------
// helpers
// ---------------------------------------------------------------------------
__device__ __forceinline__ uint32_t smem_u32(const void* p) {
    uint32_t a;
    asm("{ .reg .u64 t; cvta.to.shared.u64 t, %1; cvt.u32.u64 %0, t; }" : "=r"(a) : "l"(p));
    return a;
}
__device__ __forceinline__ float sigf(float x)   { return 1.f / (1.f + __expf(-x)); }
__device__ __forceinline__ float tanhfa(float x) { return 2.f / (1.f + __expf(-2.f * x)) - 1.f; }
__device__ __forceinline__ float tha(float x) {
    float y; asm("tanh.approx.f32 %0, %1;" : "=f"(y) : "f"(x)); return y;
}
__device__ __forceinline__ float sga(float x) { return fmaf(tha(0.5f * x), 0.5f, 0.5f); }

__device__ __forceinline__ uint32_t pack2hi(float a, float b) {
    __nv_bfloat162 h = __floats2bfloat162_rn(a, b);
    return reinterpret_cast<uint32_t&>(h);
}

__device__ __forceinline__ void ldsm4(uint32_t (&r)[4], uint32_t addr) {
    asm volatile("ldmatrix.sync.aligned.m8n8.x4.shared.b16 {%0,%1,%2,%3}, [%4];"
        : "=r"(r[0]), "=r"(r[1]), "=r"(r[2]), "=r"(r[3]) : "r"(addr));
}
__device__ __forceinline__ void mma16816(float (&c)[4], const uint32_t (&a)[4],
                                         const uint32_t b0, const uint32_t b1) {
    asm volatile("mma.sync.aligned.m16n8k16.row.col.f32.bf16.bf16.f32 "
        "{%0,%1,%2,%3}, {%4,%5,%6,%7}, {%8,%9}, {%0,%1,%2,%3};"
        : "+f"(c[0]), "+f"(c[1]), "+f"(c[2]), "+f"(c[3])
        : "r"(a[0]), "r"(a[1]), "r"(a[2]), "r"(a[3]), "r"(b0), "r"(b1));
}
__device__ __forceinline__ unsigned ldg_cg_u32(const unsigned* p) {
    unsigned v;
    asm volatile("ld.global.cg.u32 %0, [%1];" : "=r"(v) : "l"(p));
    return v;
}
__device__ __forceinline__ void lds128(uint4 &v, uint32_t addr) {
    asm volatile("ld.shared.v4.u32 {%0,%1,%2,%3}, [%4];"
        : "=r"(v.x), "=r"(v.y), "=r"(v.z), "=r"(v.w) : "r"(addr));
}

// ---------------------------------------------------------------------------
// 1-term MMA chunk: acc += A * W. NF n-fragments. (gx kernel)
// ---------------------------------------------------------------------------
template<int NF>
__device__ __forceinline__ void mma_chunk1g(
    const uint32_t aBase, const uint32_t wHi,
    const int wRowB, const int kw0, const int wm, const int wn, const int lane,
    float (&acc)[2][NF][4])
{
    const int la  = lane & 15;
    const int aKo = (lane & 16) ? 16 : 0;
    const int nB  = wn * (NF * 8) + (lane & 7) + ((lane & 16) ? 8 : 0);
    const int bKo = (lane & 8) ? 16 : 0;
    const int m0w = wm * 32;

#pragma unroll
    for (int kk = 0; kk < 4; kk++) {
        const int kb = kk * 32;
        uint32_t ah[2][4];
#pragma unroll
        for (int mf = 0; mf < 2; mf++) {
            int m = m0w + mf * 16 + la;
            uint32_t off = (uint32_t)(m * 128 + ((kb + aKo) ^ ((m & 7) << 4)));
            ldsm4(ah[mf], aBase + off);
        }
        uint32_t bh[NF][2];
#pragma unroll
        for (int nh = 0; nh < NF / 2; nh++) {
            int n = nB + nh * 16;
            uint32_t off = (uint32_t)(n * wRowB + ((kw0 + kb + bKo) ^ ((n & 7) << 4)));
            uint32_t r[4];
            ldsm4(r, wHi + off);
            bh[nh*2][0] = r[0]; bh[nh*2][1] = r[1];
            bh[nh*2+1][0] = r[2]; bh[nh*2+1][1] = r[3];
        }
#pragma unroll
        for (int mf = 0; mf < 2; mf++)
#pragma unroll
            for (int nf = 0; nf < NF; nf++)
                mma16816(acc[mf][nf], ah[mf], bh[nf][0], bh[nf][1]);
    }
}

// ---------------------------------------------------------------------------
// prep: permute W_hh/W_ih/bias to gate-interleaved columns (bf16).
// unit j, gate g: group=j/4, q=j%4 -> cols group*16 + {2q,2q+1,8+2q,9+2q}
// Also write h0 (bf16) into fragment-layout buffer 0.
// ---------------------------------------------------------------------------
__global__ void prep_kernel(const float* __restrict__ Whh, const float* __restrict__ Wih,
                            const float* __restrict__ bih, const float* __restrict__ bhh,
                            const float* __restrict__ h0)
{
    const int n = blockIdx.x;
    const int group = n >> 4, wi = n & 15;
    const int gate = ((wi >> 3) << 1) | (wi & 1);
    const int j = (group << 2) | ((wi & 7) >> 1);
    const int o = gate * HH + j;
    const int tid = threadIdx.x;

    {
        int k2 = tid * 2;
        uint32_t hi = pack2hi(Whh[(size_t)o * HH + k2], Whh[(size_t)o * HH + k2 + 1]);
        *(uint32_t*)&g_Wphi[(size_t)n * HH + k2] = hi;
    }
    if (tid < 128) {
        int k2 = tid * 2;
        uint32_t hi = pack2hi(Wih[(size_t)o * FF + k2], Wih[(size_t)o * FF + k2 + 1]);
        *(uint32_t*)&g_Wihphi[(size_t)n * FF + k2] = hi;
    }
    if (tid == 0) g_biasp[n] = bih[o] + bhh[o];
    if (n < BB) {   // h0 -> fragment layout (buffer 0)
        const int m = n;
        const int mt = m >> 6, mloc = m & 63, wm = mloc >> 4, row16 = mloc & 15;
        const int r8 = row16 & 7, aR = row16 >> 3;
#pragma unroll
        for (int e = 0; e < 2; e++) {
            int jd = tid * 2 + e;
            __nv_bfloat16 hi = __float2bfloat16(h0[(size_t)m * HH + jd]);
            int kc = jd >> 4, jc = jd & 15, p = (jc >> 1) & 3, aC = jc >> 3;
            size_t hw = ((size_t)((mt * 4 + wm) * 32 + kc) * 32 + (r8 * 4 + p)) * 8
                        + (aC * 2 + aR) * 2 + (jd & 1);
            ((__nv_bfloat16*)g_hfrag)[hw] = hi;
        }
    }
}

// ---------------------------------------------------------------------------
// Phase 1: gx = x @ Wihp^T + biasp (1-term bf16). Tile 128M x 64N, 4 iters.
// grid (32 nt, 256 mo). 8 warps: wm=w&3, wn=w>>2 (NF=4).
// smem: W 32KB @0 (rowB=512), A dbl-buf @32768 (2 x 16KB)
// ---------------------------------------------------------------------------
#define GX_SMEM 65536
__global__ void __launch_bounds__(256, 1) gx_kernel(const float* __restrict__ x)
{
    extern __shared__ char sm[];
    const uint32_t smu = smem_u32(sm);
    const int tid = threadIdx.x, w = tid >> 5, lane = tid & 31;
    const int wm = w & 3, wn = w >> 2;
    const int nt = blockIdx.x;
    const int n0 = nt * 64;
    const int q = lane & 3, r = lane >> 2;

    // resident W_ih (64 rows x 256 k, bf16): 2048 granules of 16B
#pragma unroll
    for (int i = 0; i < 8; i++) {
        int c = tid + i * 256;
        int n = c >> 5, g = c & 31;
        uint4 v = *(const uint4*)((const char*)g_Wihphi + (size_t)(n0 + n) * 512 + g * 16);
        *(uint4*)(sm + n * 512 + ((g * 16) ^ ((n & 7) << 4))) = v;
    }
    float2 bias2[4];
#pragma unroll
    for (int nf = 0; nf < 4; nf++)
        bias2[nf] = *(const float2*)&g_biasp[n0 + wn * 32 + nf * 8 + 2 * q];
    __syncthreads();

    uint4 shi[4];
#define GX_LD(kc, m0) do { \
    _Pragma("unroll") \
    for (int i2 = 0; i2 < 4; i2++) { \
        int c = tid + i2 * 256; int m = c >> 3, g = c & 7; \
        const float* sp = x + (size_t)((m0) + m) * FF + (kc) * 64 + g * 8; \
        float4 f0 = *(const float4*)sp; float4 f1 = *(const float4*)(sp + 4); \
        shi[i2].x = pack2hi(f0.x, f0.y); shi[i2].y = pack2hi(f0.z, f0.w); \
        shi[i2].z = pack2hi(f1.x, f1.y); shi[i2].w = pack2hi(f1.z, f1.w); \
    } } while (0)
#define GX_ST(buf) do { \
    _Pragma("unroll") \
    for (int i2 = 0; i2 < 4; i2++) { \
        int c = tid + i2 * 256; int m = c >> 3, g = c & 7; \
        *(uint4*)(sm + 32768 + (buf) * 16384 + m * 128 + ((g * 16) ^ ((m & 7) << 4))) = shi[i2]; \
    } } while (0)

    for (int it = 0; it < 4; it++) {
        const int m0 = blockIdx.y * 512 + it * 128;

        float acc[2][4][4];
#pragma unroll
        for (int a = 0; a < 2; a++)
#pragma unroll
            for (int b = 0; b < 4; b++)
#pragma unroll
                for (int cidx = 0; cidx < 4; cidx++) acc[a][b][cidx] = 0.f;

        GX_LD(0, m0); GX_ST(0); __syncthreads();
#pragma unroll
        for (int kc = 0; kc < 4; kc++) {
            if (kc < 3) GX_LD(kc + 1, m0);
            mma_chunk1g<4>(smu + 32768 + (kc & 1) * 16384, smu,
                           512, kc * 128, wm, wn, lane, acc);
            if (kc < 3) { GX_ST((kc + 1) & 1); __syncthreads(); }
        }

#pragma unroll
        for (int mf = 0; mf < 2; mf++)
#pragma unroll
            for (int rp = 0; rp < 2; rp++) {
                int m = m0 + wm * 32 + mf * 16 + r + rp * 8;
                int t = m & (TT - 1), b = m >> 9;
                float* dst = g_gx + ((size_t)t * BB + b) * G4;
#pragma unroll
                for (int nf = 0; nf < 4; nf++) {
                    int col = n0 + wn * 32 + nf * 8 + 2 * q;
                    *(float2*)(dst + col) =
                        make_float2(acc[mf][nf][rp*2+0] + bias2[nf].x,
                                    acc[mf][nf][rp*2+1] + bias2[nf].y);
                }
            }
        __syncthreads();
    }
}

// ---------------------------------------------------------------------------
// Phase 2: warp-autonomous persistent recurrent kernel.
// R14 base (pair-split cp.async exchange, own-half-first MMA, triple buffer)
// with QUARTER counters + STAGED waits:
//  - producers arrive (red.global, no return) at g_cntq[mt][nt>>3];
//  - reader warp wn: wait Q(2wn) -> cp.async chunks 0..7 (2 commit groups)
//    -> wait Q(2wn+1) (overlaps flight) -> cp.async chunks 8..15 (2 groups)
//    -> staged cp.async.wait_group 3/2/1/0 so MMA starts after the first
//    4 chunks land instead of all 16.
// WAR (triple buffer): me@t => my quarters' CTAs done t-1 => their
// other-half warps' t-1 waits => all mt CTAs done t-2 => all readers of
// buffer (t-2)%3 released (release follows wait_group 0). Safe.
// 128 CTAs x 256 thr; mt = bx&3, nt = bx>>2; 8 warps = 4 wm x 2 wn.
// smem: W 64KB @0; A 64KB @65536 (16KB/wm); pack scratch 2KB @131072.
// ---------------------------------------------------------------------------
#define LSTM_SMEM 133120
__global__ void __launch_bounds__(256, 1) lstm_kernel(const float* __restrict__ c0)
{
    extern __shared__ char sm[];
    const uint32_t smu = smem_u32(sm);
    const int tid = threadIdx.x, w = tid >> 5, lane = tid & 31;
    const int wm = w & 3, wn = w >> 2;
    const int bx = blockIdx.x;
    const int mt = bx & 3, nt = bx >> 2;
    const int m0 = mt * 64, n0 = nt * 64;
    const int q = lane & 3, r = lane >> 2;
    const unsigned* cntQ0 = &g_cntq[(mt * 4 + 2 * wn) * 32];       // producers of chunks kb..kb+7
    const unsigned* cntQ1 = &g_cntq[(mt * 4 + 2 * wn + 1) * 32];   // producers of chunks kb+8..kb+15
    unsigned* cntMine = &g_cntq[(mt * 4 + (nt >> 3)) * 32];        // quarter I produce

    // resident W (64 perm-cols x 512 k, bf16)
#pragma unroll
    for (int i = 0; i < 16; i++) {
        int c = tid + i * 256;
        int n = c >> 6, g = c & 63;
        uint4 v = *(const uint4*)((const char*)g_Wphi + (size_t)(n0 + n) * 1024 + g * 16);
        *(uint4*)(sm + n * 1024 + ((g * 16) ^ ((n & 7) << 4))) = v;
    }

    const int mr0 = m0 + wm * 16 + r;
    const int unitA = (nt * 4 + wn * 2) * 4 + q;
    const int unitB = unitA + 4;

    float creg[4];
    creg[0] = c0[(size_t)mr0 * HH + unitA];
    creg[1] = c0[(size_t)(mr0 + 8) * HH + unitA];
    creg[2] = c0[(size_t)mr0 * HH + unitB];
    creg[3] = c0[(size_t)(mr0 + 8) * HH + unitB];
    __syncthreads();    // W resident ready (only CTA-wide sync; outside the loop)

    // ldsm W addressing
    const int nW1 = wn * 32 + (lane & 7) + ((lane & 16) ? 8 : 0);
    const int nW2 = nW1 + 16;
    const int bKo = (lane & 8) ? 16 : 0;
    const uint32_t wb1 = smu + nW1 * 1024;
    const uint32_t wb2 = smu + nW2 * 1024;
    const int sw1 = (nW1 & 7) << 4, sw2 = (nW2 & 7) << 4;

    const int colA = n0 + wn * 32 + 2 * q;
    const int fragbase = ((mt * 4 + wm) * 32) * 32 + lane;
    const uint32_t aReg = smu + 65536 + (uint32_t)wm * 16384;   // per-wm A region
    const uint32_t aLane = aReg + (uint32_t)lane * 16;
    const uint32_t ps = smu + 131072 + w * 256;

    int br = 0;   // t % 3

    for (int t = 0; t < TT; t++) {
        // ---- gx loads (immutable; issued before the wait, overlap polling) ----
        const float* gp0 = g_gx + ((size_t)t * BB + mr0) * G4;
        const float* gp1 = gp0 + 8 * G4;
        float2 ifA0 = *(const float2*)(gp0 + colA);
        float2 goA0 = *(const float2*)(gp0 + colA + 8);
        float2 ifB0 = *(const float2*)(gp0 + colA + 16);
        float2 goB0 = *(const float2*)(gp0 + colA + 24);
        float2 ifA1 = *(const float2*)(gp1 + colA);
        float2 goA1 = *(const float2*)(gp1 + colA + 8);
        float2 ifB1 = *(const float2*)(gp1 + colA + 16);
        float2 goB1 = *(const float2*)(gp1 + colA + 24);

        const unsigned tgt = (unsigned)t * 64u;
        const uint4* hin = &g_hfrag[br][fragbase];
        const int kb = wn * 16;

        // ---- wait quarter 0 (fan-in 64), then launch its 8 chunks ----
        if (t) {
            unsigned cur = ldg_cg_u32(cntQ0);
            while (cur < tgt) { __nanosleep(32); cur = ldg_cg_u32(cntQ0); }
        }
#pragma unroll
        for (int i = 0; i < 8; i++) {
            const int kc = kb + i;
            uint32_t dst = aReg + (uint32_t)(kc * 512 + lane * 16);
            const uint4* src = hin + kc * 32;
            asm volatile("cp.async.cg.shared.global [%0], [%1], 16;"
                         :: "r"(dst), "l"(src) : "memory");
            if (i == 3) asm volatile("cp.async.commit_group;" ::: "memory");
        }
        asm volatile("cp.async.commit_group;" ::: "memory");

        // ---- wait quarter 1 (overlaps quarter-0 flight), launch its 8 ----
        if (t) {
            unsigned cur = ldg_cg_u32(cntQ1);
            while (cur < tgt) { __nanosleep(32); cur = ldg_cg_u32(cntQ1); }
        }
#pragma unroll
        for (int i = 8; i < 16; i++) {
            const int kc = kb + i;
            uint32_t dst = aReg + (uint32_t)(kc * 512 + lane * 16);
            const uint4* src = hin + kc * 32;
            asm volatile("cp.async.cg.shared.global [%0], [%1], 16;"
                         :: "r"(dst), "l"(src) : "memory");
            if (i == 11) asm volatile("cp.async.commit_group;" ::: "memory");
        }
        asm volatile("cp.async.commit_group;" ::: "memory");

        float acc[4][4];
#pragma unroll
        for (int a = 0; a < 4; a++)
#pragma unroll
            for (int cix = 0; cix < 4; cix++) acc[a][cix] = 0.f;

        // ---- half 1: OWN chunks, staged group waits ----
        {
            uint4 ab[4];
            asm volatile("cp.async.wait_group 3;" ::: "memory");   // chunks 0-3 ready
#pragma unroll
            for (int i = 0; i < 4; i++) lds128(ab[i], aLane + (uint32_t)((kb + i) * 512));
            asm volatile("cp.async.wait_group 2;" ::: "memory");   // 4-7 ready (prefetch-safe)
#pragma unroll
            for (int i = 0; i < 16; i++) {
                const int kc = kb + i;
                uint32_t au[4] = { ab[i & 3].x, ab[i & 3].y, ab[i & 3].z, ab[i & 3].w };
                if (i < 12) lds128(ab[i & 3], aLane + (uint32_t)((kc + 4) * 512));
                uint32_t rA[4], rB[4];
                ldsm4(rA, wb1 + (uint32_t)((kc * 32 + bKo) ^ sw1));
                ldsm4(rB, wb2 + (uint32_t)((kc * 32 + bKo) ^ sw2));
                mma16816(acc[0], au, rA[0], rA[1]);
                mma16816(acc[1], au, rA[2], rA[3]);
                mma16816(acc[2], au, rB[0], rB[1]);
                mma16816(acc[3], au, rB[2], rB[3]);
                if (i == 3) asm volatile("cp.async.wait_group 1;" ::: "memory");  // 8-11
                if (i == 7) asm volatile("cp.async.wait_group 0;" ::: "memory");  // 12-15
            }
        }

        // ---- pair barrier: partner's half landed during our half 1 ----
        asm volatile("bar.sync %0, 64;" :: "r"(wm + 1) : "memory");

        // ---- half 2: PARTNER chunks (all resident in smem) ----
        {
            const int kb2 = (wn ^ 1) * 16;
            uint4 ab[4];
#pragma unroll
            for (int i = 0; i < 4; i++) lds128(ab[i], aLane + (uint32_t)((kb2 + i) * 512));
#pragma unroll
            for (int i = 0; i < 16; i++) {
                const int kc = kb2 + i;
                uint32_t au[4] = { ab[i & 3].x, ab[i & 3].y, ab[i & 3].z, ab[i & 3].w };
                if (i < 12) lds128(ab[i & 3], aLane + (uint32_t)((kc + 4) * 512));
                uint32_t rA[4], rB[4];
                ldsm4(rA, wb1 + (uint32_t)((kc * 32 + bKo) ^ sw1));
                ldsm4(rB, wb2 + (uint32_t)((kc * 32 + bKo) ^ sw2));
                mma16816(acc[0], au, rA[0], rA[1]);
                mma16816(acc[1], au, rA[2], rA[3]);
                mma16816(acc[2], au, rB[0], rB[1]);
                mma16816(acc[3], au, rB[2], rB[3]);
            }
        }

        // ---- epilogue: gates + state update (approx gates; exact last step) ----
        const bool last = (t == TT - 1);
        float hv[4];
        float sI[4], sF[4], sG[4], sO[4];
        sI[0] = acc[0][0] + ifA0.x;  sF[0] = acc[0][1] + ifA0.y;
        sG[0] = acc[1][0] + goA0.x;  sO[0] = acc[1][1] + goA0.y;
        sI[1] = acc[0][2] + ifA1.x;  sF[1] = acc[0][3] + ifA1.y;
        sG[1] = acc[1][2] + goA1.x;  sO[1] = acc[1][3] + goA1.y;
        sI[2] = acc[2][0] + ifB0.x;  sF[2] = acc[2][1] + ifB0.y;
        sG[2] = acc[3][0] + goB0.x;  sO[2] = acc[3][1] + goB0.y;
        sI[3] = acc[2][2] + ifB1.x;  sF[3] = acc[2][3] + ifB1.y;
        sG[3] = acc[3][2] + goB1.x;  sO[3] = acc[3][3] + goB1.y;
#pragma unroll
        for (int cell = 0; cell < 4; cell++) {
            float iv, fv, gv, ov, cc;
            if (!last) {
                iv = sga(sI[cell]); fv = sga(sF[cell]);
                gv = tha(sG[cell]); ov = sga(sO[cell]);
                cc = fv * creg[cell] + iv * gv;
                hv[cell] = ov * tha(cc);
            } else {
                iv = sigf(sI[cell]); fv = sigf(sF[cell]);
                gv = tanhfa(sG[cell]); ov = sigf(sO[cell]);
                cc = fv * creg[cell] + iv * gv;
                hv[cell] = ov * tanhfa(cc);
            }
            creg[cell] = cc;
        }

        // ---- pack h into A-fragment words (warp-local smem), publish ----
#pragma unroll
        for (int cell = 0; cell < 4; cell++) {
            int rp = cell & 1, g = cell >> 1;
            unsigned short hb;
            __nv_bfloat16 b16 = __float2bfloat16(hv[cell]);
            hb = *(unsigned short*)&b16;
            uint32_t addr = ps + (uint32_t)((r + rp * 8) * 16 + (g * 4 + q) * 2);
            asm volatile("st.shared.u16 [%0], %1;" :: "r"(addr), "h"(hb));
        }
        __syncwarp();
        const int bw = (br + 1 == 3) ? 0 : br + 1;
        {
            uint32_t v0, v1;
            asm volatile("ld.shared.u32 %0, [%1];" : "=r"(v0)
                         : "r"(ps + (uint32_t)((lane >> 2) * 16 + (lane & 3) * 4)));
            asm volatile("ld.shared.u32 %0, [%1];" : "=r"(v1)
                         : "r"(ps + (uint32_t)(((lane >> 2) + 8) * 16 + (lane & 3) * 4)));
            uint2 outw = make_uint2(v0, v1);
            uint2* hop = (uint2*)&g_hfrag[bw][((mt * 4 + wm) * 32 + nt) * 32];
            hop[lane * 2 + wn] = outw;
        }

        if (last) {   // also publish original-layout h (hi+lo) for fc
#pragma unroll
            for (int cell = 0; cell < 4; cell++) {
                int rp = cell & 1, g = cell >> 1;
                int m = mr0 + rp * 8;
                int u = g ? unitB : unitA;
                __nv_bfloat16 hi = __float2bfloat16(hv[cell]);
                g_hhi[(size_t)m * HH + u] = hi;
                g_hlo[(size_t)m * HH + u] = __float2bfloat16(hv[cell] - __bfloat162float(hi));
            }
        }

        // ---- per-warp release: fence + REDG arrive on my quarter ----
        __threadfence();
        if (lane == 0)
            asm volatile("red.global.add.u32 [%0], 1;" :: "l"(cntMine) : "memory");
        br = bw;
    }
}

// ---------------------------------------------------------------------------
// Phase 3: out[b][e] = sigmoid(hT[b][:] . W_fc[e][:] + b_fc[e]); h = hi + lo
// ---------------------------------------------------------------------------
__global__ void __launch_bounds__(128) fc_kernel(
    const float* __restrict__ Wfc, const float* __restrict__ bfc,
    float* __restrict__ out)
{
    __shared__ float hs[HH];
    const int b = blockIdx.x;
    const int tid = threadIdx.x;
    for (int k = tid; k < HH; k += 128)
        hs[k] = __bfloat162float(g_hhi[(size_t)b * HH + k]) +
                __bfloat162float(g_hlo[(size_t)b * HH + k]);
    __syncthreads();

    float acc = bfc[tid];
    const float* wp = Wfc + (size_t)tid * HH;
#pragma unroll 4
    for (int k = 0; k < HH; k += 4) {
        float4 w4 = *(const float4*)(wp + k);
        acc += hs[k] * w4.x + hs[k+1] * w4.y + hs[k+2] * w4.z + hs[k+3] * w4.w;
    }
    out[b * EE + tid] = sigf(acc);
}

// ---------------------------------------------------------------------------
extern "C" void kernel_launch(void* const* d_in, const int* in_sizes, int n_in,
                              void* d_out, int out_size) {
    const float* x   = (const float*)d_in[0];
    const float* h0  = (const float*)d_in[1];
    const float* c0  = (const float*)d_in[2];
    const float* Wih = (const float*)d_in[3];
    const float* Whh = (const float*)d_in[4];
    const float* bih = (const float*)d_in[5];
    const float* bhh = (const float*)d_in[6];
    const float* Wfc = (const float*)d_in[7];
    const float* bfc = (const float*)d_in[8];
    (void)in_sizes; (void)n_in; (void)out_size;

    cudaFuncSetAttribute(gx_kernel,   cudaFuncAttributeMaxDynamicSharedMemorySize, GX_SMEM);
    cudaFuncSetAttribute(lstm_kernel, cudaFuncAttributeMaxDynamicSharedMemorySize, LSTM_SMEM);

    void* pcnt = nullptr;
    cudaGetSymbolAddress(&pcnt, g_cntq);
    cudaMemsetAsync(pcnt, 0, sizeof(unsigned) * 4 * 4 * 32, 0);

    prep_kernel<<<G4, 256>>>(Whh, Wih, bih, bhh, h0);
    gx_kernel<<<dim3(32, 256), 256, GX_SMEM>>>(x);
    lstm_kernel<<<NREC, 256, LSTM_SMEM>>>(c0);
    fc_kernel<<<BB, EE>>>(Wfc, bfc, (float*)d_out);
}